// round 3
// baseline (speedup 1.0000x reference)
#include <cuda_runtime.h>
#include <math.h>

// ---------------------------------------------------------------------------
// Model constants
// ---------------------------------------------------------------------------
#define Tn  128
#define Dn  1024
#define Ln  8
#define Hn  16
#define Fn  2816
#define DHn 64
#define Vn  32000

// ---------------------------------------------------------------------------
// Scratch (device globals: allocation-free per harness rules)
// ---------------------------------------------------------------------------
__device__ float g_X [Tn * Dn];        // residual stream
__device__ float g_XN[Tn * Dn];        // rmsnorm output
__device__ float g_Q [Tn * Dn];
__device__ float g_Kc[Tn * Dn];
__device__ float g_Vc[Tn * Dn];
__device__ float g_A [Tn * Dn];        // attention output (pre-Wo)
__device__ float g_H [Tn * Fn];        // silu(gate)*up
__device__ float g_part[4 * Tn * Fn];  // split-K / gate-up partials (5.77 MB)
__device__ float g_xl[Dn];             // final normed hidden (last token)

// ---------------------------------------------------------------------------
// Helpers
// ---------------------------------------------------------------------------
__device__ __forceinline__ float blockReduceSum(float v) {
    __shared__ float red[32];
    __shared__ float tot;
    int lane = threadIdx.x & 31, warp = threadIdx.x >> 5;
#pragma unroll
    for (int o = 16; o > 0; o >>= 1) v += __shfl_xor_sync(0xffffffffu, v, o);
    if (lane == 0) red[warp] = v;
    __syncthreads();
    int nw = (blockDim.x + 31) >> 5;
    if (warp == 0) {
        float x = (threadIdx.x < nw) ? red[threadIdx.x] : 0.f;
#pragma unroll
        for (int o = 16; o > 0; o >>= 1) x += __shfl_xor_sync(0xffffffffu, x, o);
        if (threadIdx.x == 0) tot = x;
    }
    __syncthreads();
    return tot;
}

// ---------------------------------------------------------------------------
// Embedding gather: g_X[t,:] = emb[ids[t],:]
// ---------------------------------------------------------------------------
__global__ void k_embed(const int* __restrict__ ids, const float* __restrict__ emb) {
    int t = blockIdx.x;
    int row = ids[t];
    const float4* src = (const float4*)(emb + (size_t)row * Dn);
    float4* dst = (float4*)(g_X + (size_t)t * Dn);
    for (int i = threadIdx.x; i < Dn / 4; i += blockDim.x) dst[i] = src[i];
}

// ---------------------------------------------------------------------------
// RMSNorm: g_XN[t,:] = g_X[t,:] * rsqrt(mean(x^2)+eps) * w
// grid = Tn, block = 256
// ---------------------------------------------------------------------------
__global__ void k_rmsnorm(const float* __restrict__ w) {
    int t = blockIdx.x;
    const float4* x4 = (const float4*)(g_X + (size_t)t * Dn);
    const float4* w4 = (const float4*)w;
    float4* o4 = (float4*)(g_XN + (size_t)t * Dn);
    float4 xv = x4[threadIdx.x];                    // 256 threads * 4 = 1024
    float ss = xv.x * xv.x + xv.y * xv.y + xv.z * xv.z + xv.w * xv.w;
    ss = blockReduceSum(ss);
    float inv = rsqrtf(ss / (float)Dn + 1e-5f);
    float4 wv = w4[threadIdx.x];
    float4 r = make_float4(xv.x * inv * wv.x, xv.y * inv * wv.y,
                           xv.z * inv * wv.z, xv.w * inv * wv.w);
    o4[threadIdx.x] = r;
}

// Final rmsnorm of last token into g_xl
__global__ void k_finalnorm(const float* __restrict__ w) {
    const float4* x4 = (const float4*)(g_X + (size_t)(Tn - 1) * Dn);
    const float4* w4 = (const float4*)w;
    float4* o4 = (float4*)g_xl;
    float4 xv = x4[threadIdx.x];
    float ss = xv.x * xv.x + xv.y * xv.y + xv.z * xv.z + xv.w * xv.w;
    ss = blockReduceSum(ss);
    float inv = rsqrtf(ss / (float)Dn + 1e-5f);
    float4 wv = w4[threadIdx.x];
    o4[threadIdx.x] = make_float4(xv.x * inv * wv.x, xv.y * inv * wv.y,
                                  xv.z * inv * wv.z, xv.w * inv * wv.w);
}

// ---------------------------------------------------------------------------
// SGEMM core: 64x64 block tile, BK=16, 256 threads, 4x4 per-thread microtile,
// single-stage smem with register prefetch of next tile.
// A: row-major [.., lda], B: row-major [.., ldb], C: row-major [.., ldc]
// All dims here divide evenly (M=128, N in {1024,2816}, kc multiple of 16).
// ---------------------------------------------------------------------------
__device__ __forceinline__ void gemm_block(
    const float* __restrict__ A, int lda,
    const float* __restrict__ B, int ldb,
    float* __restrict__ C, int ldc, int kc)
{
    __shared__ float As[16][64];
    __shared__ float Bs[16][64];
    const int m0 = blockIdx.y * 64, n0 = blockIdx.x * 64;
    const int tid = threadIdx.x;
    const int ar = tid >> 2, ac = (tid & 3) << 2;   // A tile: 64 rows x 16 cols
    const int br = tid >> 4, bc = (tid & 15) << 2;  // B tile: 16 rows x 64 cols
    const int ty = tid >> 4, tx = tid & 15;

    float4 aReg = *(const float4*)(A + (size_t)(m0 + ar) * lda + ac);
    float4 bReg = *(const float4*)(B + (size_t)br * ldb + n0 + bc);

    float acc[4][4] = {};

    for (int kk = 0; kk < kc; kk += 16) {
        As[ac + 0][ar] = aReg.x; As[ac + 1][ar] = aReg.y;
        As[ac + 2][ar] = aReg.z; As[ac + 3][ar] = aReg.w;
        *(float4*)&Bs[br][bc] = bReg;
        __syncthreads();
        if (kk + 16 < kc) {
            aReg = *(const float4*)(A + (size_t)(m0 + ar) * lda + (kk + 16) + ac);
            bReg = *(const float4*)(B + (size_t)(kk + 16 + br) * ldb + n0 + bc);
        }
#pragma unroll
        for (int k = 0; k < 16; k++) {
            float a[4], b[4];
#pragma unroll
            for (int j = 0; j < 4; j++) a[j] = As[k][(ty << 2) + j];
#pragma unroll
            for (int j = 0; j < 4; j++) b[j] = Bs[k][(tx << 2) + j];
#pragma unroll
            for (int ii = 0; ii < 4; ii++)
#pragma unroll
                for (int jj = 0; jj < 4; jj++)
                    acc[ii][jj] = fmaf(a[ii], b[jj], acc[ii][jj]);
        }
        __syncthreads();
    }
#pragma unroll
    for (int ii = 0; ii < 4; ii++) {
        float4 v = make_float4(acc[ii][0], acc[ii][1], acc[ii][2], acc[ii][3]);
        *(float4*)(C + (size_t)(m0 + (ty << 2) + ii) * ldc + n0 + (tx << 2)) = v;
    }
}

// QKV: grid (16, 2, 3), A = g_XN [128,1024]
__global__ void k_qkv(const float* __restrict__ Wq, const float* __restrict__ Wk,
                      const float* __restrict__ Wv) {
    const float* B = (blockIdx.z == 0) ? Wq : (blockIdx.z == 1) ? Wk : Wv;
    float* C = (blockIdx.z == 0) ? g_Q : (blockIdx.z == 1) ? g_Kc : g_Vc;
    gemm_block(g_XN, Dn, B, Dn, C, Dn, Dn);
}

// Split-K=4 GEMM into g_part. aSel: 0 -> A=g_A (K=1024), 1 -> A=g_H (K=2816)
__global__ void k_gemm_split4(int aSel, const float* __restrict__ B, int N, int K) {
    const float* A = aSel ? g_H : g_A;
    int lda = aSel ? Fn : Dn;
    int kc = K >> 2;
    int k0 = blockIdx.z * kc;
    gemm_block(A + k0, lda, B + (size_t)k0 * N, N,
               g_part + (size_t)blockIdx.z * Tn * N, N, kc);
}

// Gate/Up fused, split-K=2 each. z = mat*2 + split. grid (44, 2, 4)
__global__ void k_gateup(const float* __restrict__ Wg, const float* __restrict__ Wu) {
    int mat = blockIdx.z >> 1, sp = blockIdx.z & 1;
    const float* Bp = mat ? Wu : Wg;
    int kc = Dn >> 1;
    int k0 = sp * kc;
    gemm_block(g_XN + k0, Dn, Bp + (size_t)k0 * Fn, Fn,
               g_part + (size_t)blockIdx.z * Tn * Fn, Fn, kc);
}

// Residual add with split-K reduce: g_X += sum_z g_part[z]
__global__ void k_reduceX() {
    int i = blockIdx.x * blockDim.x + threadIdx.x;
    g_X[i] += g_part[i] + g_part[Tn * Dn + i]
            + g_part[2 * Tn * Dn + i] + g_part[3 * Tn * Dn + i];
}

// SiLU(gate)*up with gate/up split-K reduce fused
__global__ void k_silu() {
    int i = blockIdx.x * blockDim.x + threadIdx.x;
    float g = g_part[i] + g_part[Tn * Fn + i];
    float u = g_part[2 * Tn * Fn + i] + g_part[3 * Tn * Fn + i];
    float s = g / (1.f + expf(-g));
    g_H[i] = s * u;
}

// ---------------------------------------------------------------------------
// RoPE on Q and K. grid = Tn, block = 512 (16 heads x 32 rotation pairs)
// out[d]    = x[d]*cos - x[d+32]*sin
// out[d+32] = x[d+32]*cos + x[d]*sin,  angle = t * base^(-d/32)
// ---------------------------------------------------------------------------
__global__ void k_rope() {
    int t = blockIdx.x;
    int h = threadIdx.x >> 5;
    int d = threadIdx.x & 31;
    double inv = pow(10000.0, -(double)d / 32.0);
    double ang = (double)t * inv;
    float c = (float)cos(ang), s = (float)sin(ang);
    int i0 = t * Dn + h * DHn + d, i1 = i0 + 32;
    float q0 = g_Q[i0], q1 = g_Q[i1];
    g_Q[i0] = q0 * c - q1 * s;
    g_Q[i1] = q1 * c + q0 * s;
    float k0 = g_Kc[i0], k1 = g_Kc[i1];
    g_Kc[i0] = k0 * c - k1 * s;
    g_Kc[i1] = k1 * c + k0 * s;
}

// ---------------------------------------------------------------------------
// Causal attention, exact softmax. grid (Tn, Hn), block 128.
// K (then V) staged in padded smem; matches reference -1e9 masking.
// ---------------------------------------------------------------------------
__global__ void k_attn() {
    int i = blockIdx.x, h = blockIdx.y;
    int tid = threadIdx.x;
    __shared__ float q[DHn];
    __shared__ float KV[Tn][DHn + 1];
    __shared__ float p[Tn];
    __shared__ float rmax[4], rsum[4];

    if (tid < DHn) q[tid] = g_Q[(size_t)i * Dn + h * DHn + tid];
    for (int idx = tid; idx < Tn * DHn; idx += 128) {
        int r = idx >> 6, c = idx & 63;
        KV[r][c] = g_Kc[(size_t)r * Dn + h * DHn + c];
    }
    __syncthreads();

    float sc;
    if (tid <= i) {
        float s = 0.f;
#pragma unroll
        for (int d = 0; d < DHn; d++) s = fmaf(q[d], KV[tid][d], s);
        sc = s * 0.125f;                     // 1/sqrt(64)
    } else {
        sc = -1e9f;
    }

    float m = sc;
#pragma unroll
    for (int o = 16; o > 0; o >>= 1) m = fmaxf(m, __shfl_xor_sync(0xffffffffu, m, o));
    if ((tid & 31) == 0) rmax[tid >> 5] = m;
    __syncthreads();
    m = fmaxf(fmaxf(rmax[0], rmax[1]), fmaxf(rmax[2], rmax[3]));

    float e = expf(sc - m);
    float s = e;
#pragma unroll
    for (int o = 16; o > 0; o >>= 1) s += __shfl_xor_sync(0xffffffffu, s, o);
    if ((tid & 31) == 0) rsum[tid >> 5] = s;
    __syncthreads();
    s = rsum[0] + rsum[1] + rsum[2] + rsum[3];
    p[tid] = e / s;
    __syncthreads();

    // stage V over K
    for (int idx = tid; idx < Tn * DHn; idx += 128) {
        int r = idx >> 6, c = idx & 63;
        KV[r][c] = g_Vc[(size_t)r * Dn + h * DHn + c];
    }
    __syncthreads();

    if (tid < DHn) {
        float o = 0.f;
#pragma unroll 8
        for (int j = 0; j < Tn; j++) o = fmaf(p[j], KV[j][tid], o);
        g_A[(size_t)i * Dn + h * DHn + tid] = o;
    }
}

// ---------------------------------------------------------------------------
// Tied lm_head GEMV: logits[v] = dot(emb[v,:], g_xl). One warp per row.
// grid = Vn/8, block = 256 (8 warps)
// ---------------------------------------------------------------------------
__global__ void k_logits(const float* __restrict__ emb, float* __restrict__ out) {
    __shared__ float4 xs[Dn / 4];
    for (int i = threadIdx.x; i < Dn / 4; i += blockDim.x)
        xs[i] = ((const float4*)g_xl)[i];
    __syncthreads();
    int warp = threadIdx.x >> 5, lane = threadIdx.x & 31;
    int row = blockIdx.x * 8 + warp;
    if (row < Vn) {
        const float4* e4 = (const float4*)(emb + (size_t)row * Dn);
        float s = 0.f;
#pragma unroll
        for (int k = lane; k < Dn / 4; k += 32) {
            float4 a = e4[k], b = xs[k];
            s += a.x * b.x + a.y * b.y + a.z * b.z + a.w * b.w;
        }
#pragma unroll
        for (int o = 16; o > 0; o >>= 1) s += __shfl_xor_sync(0xffffffffu, s, o);
        if (lane == 0) out[row] = s;
    }
}

// ---------------------------------------------------------------------------
// Host orchestration (graph-capturable: kernel launches only)
// ---------------------------------------------------------------------------
extern "C" void kernel_launch(void* const* d_in, const int* in_sizes, int n_in,
                              void* d_out, int out_size) {
    const int*   ids       = (const int*)  d_in[0];
    const float* emb       = (const float*)d_in[1];
    const float* Wq        = (const float*)d_in[2];
    const float* Wk        = (const float*)d_in[3];
    const float* Wv        = (const float*)d_in[4];
    const float* Wo        = (const float*)d_in[5];
    const float* Wg        = (const float*)d_in[6];
    const float* Wu        = (const float*)d_in[7];
    const float* Wd        = (const float*)d_in[8];
    const float* attn_norm = (const float*)d_in[9];
    const float* ffn_norm  = (const float*)d_in[10];
    const float* norm_out  = (const float*)d_in[11];
    float* out = (float*)d_out;

    k_embed<<<Tn, 256>>>(ids, emb);

    for (int l = 0; l < Ln; l++) {
        const float* wq = Wq + (size_t)l * Dn * Dn;
        const float* wk = Wk + (size_t)l * Dn * Dn;
        const float* wv = Wv + (size_t)l * Dn * Dn;
        const float* wo = Wo + (size_t)l * Dn * Dn;
        const float* wg = Wg + (size_t)l * Dn * Fn;
        const float* wu = Wu + (size_t)l * Dn * Fn;
        const float* wd = Wd + (size_t)l * Fn * Dn;

        k_rmsnorm<<<Tn, 256>>>(attn_norm + (size_t)l * Dn);
        k_qkv<<<dim3(Dn / 64, Tn / 64, 3), 256>>>(wq, wk, wv);
        k_rope<<<Tn, 512>>>();
        k_attn<<<dim3(Tn, Hn), 128>>>();
        k_gemm_split4<<<dim3(Dn / 64, Tn / 64, 4), 256>>>(0, wo, Dn, Dn);
        k_reduceX<<<(Tn * Dn) / 256, 256>>>();

        k_rmsnorm<<<Tn, 256>>>(ffn_norm + (size_t)l * Dn);
        k_gateup<<<dim3(Fn / 64, Tn / 64, 4), 256>>>(wg, wu);
        k_silu<<<(Tn * Fn) / 256, 256>>>();
        k_gemm_split4<<<dim3(Dn / 64, Tn / 64, 4), 256>>>(1, wd, Dn, Fn);
        k_reduceX<<<(Tn * Dn) / 256, 256>>>();
    }

    k_finalnorm<<<1, 256>>>(norm_out);
    k_logits<<<(Vn + 7) / 8, 256>>>(emb, out);
}

// round 6
// speedup vs baseline: 1.3742x; 1.3742x over previous
#include <cuda_runtime.h>
#include <cuda_bf16.h>
#include <math.h>
#include <stdint.h>

#define Tn  128
#define Dn  1024
#define Ln  8
#define Hn  16
#define Fn  2816
#define DHn 64
#define Vn  32000
#define TnDn (Tn*Dn)
#define TnFn (Tn*Fn)

// ---- scratch ----
__device__ float g_X [TnDn];
__device__ float g_Q [TnDn];
__device__ float g_Kc[TnDn];
__device__ float g_Vc[TnDn];
__device__ float g_part[12 * TnDn];
__device__ float g_xl[Dn];
__device__ __nv_bfloat16 g_XNh[TnDn], g_XNl[TnDn];
__device__ __nv_bfloat16 g_Ah [TnDn], g_Al [TnDn];
__device__ __nv_bfloat16 g_Hh [TnFn], g_Hl [TnFn];

// ---- helpers ----
__device__ __forceinline__ uint32_t smem_u32(const void* p) {
    uint32_t a;
    asm("{ .reg .u64 t; cvta.to.shared.u64 t, %1; cvt.u32.u64 %0, t; }" : "=r"(a) : "l"(p));
    return a;
}
#define LDSM_X4(r0, r1, r2, r3, a) \
    asm volatile("ldmatrix.sync.aligned.m8n8.x4.shared.b16 {%0,%1,%2,%3}, [%4];" \
                 : "=r"(r0), "=r"(r1), "=r"(r2), "=r"(r3) : "r"(a))

__device__ __forceinline__ void mma_bf16(float* d, const uint32_t* a, const uint32_t* b) {
    asm volatile("mma.sync.aligned.m16n8k16.row.col.f32.bf16.bf16.f32 "
                 "{%0,%1,%2,%3}, {%4,%5,%6,%7}, {%8,%9}, {%0,%1,%2,%3};"
                 : "+f"(d[0]), "+f"(d[1]), "+f"(d[2]), "+f"(d[3])
                 : "r"(a[0]), "r"(a[1]), "r"(a[2]), "r"(a[3]), "r"(b[0]), "r"(b[1]));
}

// ---- GEMM core: C_tile[128 x 64] = Ahl[128,K] * W[K, n0..n0+64), hi/lo bf16 ----
// smem layout (dynamic): pitch 72 bf16 (144B) rows
#define PITCHB 144
#define OFF_AH 0
#define OFF_AL 18432
#define OFF_BH 36864
#define OFF_BL 46080
#define SMEM_BYTES 55296

__device__ void gemm_core(const __nv_bfloat16* __restrict__ Ah,
                          const __nv_bfloat16* __restrict__ Al, int lda,
                          const float* __restrict__ B, int ldb,
                          float* __restrict__ Cp, int ldc,
                          int k0, int nkb, int n0)
{
    extern __shared__ unsigned char sm[];
    const uint32_t smb = smem_u32(sm);
    const int tid = threadIdx.x, wid = tid >> 5, lane = tid & 31;
    const int gID = lane >> 2, tig = lane & 3;

    float c[2][8][4];
#pragma unroll
    for (int mt = 0; mt < 2; mt++)
#pragma unroll
        for (int nt = 0; nt < 8; nt++)
#pragma unroll
            for (int i = 0; i < 4; i++) c[mt][nt][i] = 0.f;

    const int bkk0 = (tid & 7) << 3;   // B: 8-k subgroup
    const int bn4  = (tid >> 3) << 2;  // B: 4 consecutive n

    // ldmatrix lane addressing (precomputed pieces)
    const int a_r = lane & 15, a_h = lane >> 4;
    const int b_nr = ((lane >> 4) << 3) | (lane & 7);  // n row within tile pair
    const int b_kh = (lane >> 3) & 1;

    for (int it = 0; it < nkb; ++it) {
        if (it) __syncthreads();       // compute(it-1) done before restaging
        const int kc = k0 + it * 64;

        // ---- stage A hi/lo: 128 rows x 64 bf16, pitch 72 ----
#pragma unroll
        for (int j = 0; j < 8; j++) {
            int ch = j * 128 + tid;
            int m = ch >> 3, k8 = (ch & 7) << 3;
            uint32_t off = (uint32_t)m * PITCHB + k8 * 2;
            *(uint4*)(sm + OFF_AH + off) = *(const uint4*)(Ah + (size_t)m * lda + kc + k8);
            *(uint4*)(sm + OFF_AL + off) = *(const uint4*)(Al + (size_t)m * lda + kc + k8);
        }
        // ---- stage B transposed: Bs[n][k] = W[kc+k][n0+n], cvt hi/lo ----
        float4 f[8];
#pragma unroll
        for (int j = 0; j < 8; j++)
            f[j] = *(const float4*)(B + (size_t)(kc + bkk0 + j) * ldb + n0 + bn4);
#pragma unroll
        for (int i = 0; i < 4; i++) {
            union { __nv_bfloat16 b[8]; uint4 v; } hb, lb;
#pragma unroll
            for (int j = 0; j < 8; j++) {
                float x = (i == 0) ? f[j].x : (i == 1) ? f[j].y : (i == 2) ? f[j].z : f[j].w;
                __nv_bfloat16 hh = __float2bfloat16(x);
                hb.b[j] = hh;
                lb.b[j] = __float2bfloat16(x - __bfloat162float(hh));
            }
            uint32_t off = (uint32_t)(bn4 + i) * PITCHB + bkk0 * 2;
            *(uint4*)(sm + OFF_BH + off) = hb.v;
            *(uint4*)(sm + OFF_BL + off) = lb.v;
        }
        __syncthreads();

        // ---- compute 4 k-steps of 16 ----
#pragma unroll
        for (int s = 0; s < 4; s++) {
            uint32_t ah[2][4], al[2][4], bh[8][2], bl[8][2];
#pragma unroll
            for (int mt = 0; mt < 2; mt++) {
                uint32_t ao = (uint32_t)(wid * 32 + mt * 16 + a_r) * PITCHB
                            + (s * 16 + a_h * 8) * 2;
                LDSM_X4(ah[mt][0], ah[mt][1], ah[mt][2], ah[mt][3], smb + OFF_AH + ao);
                LDSM_X4(al[mt][0], al[mt][1], al[mt][2], al[mt][3], smb + OFF_AL + ao);
            }
#pragma unroll
            for (int np = 0; np < 4; np++) {
                uint32_t bo = (uint32_t)(np * 16 + b_nr) * PITCHB
                            + (s * 16 + b_kh * 8) * 2;
                LDSM_X4(bh[np*2][0], bh[np*2][1], bh[np*2+1][0], bh[np*2+1][1],
                        smb + OFF_BH + bo);
                LDSM_X4(bl[np*2][0], bl[np*2][1], bl[np*2+1][0], bl[np*2+1][1],
                        smb + OFF_BL + bo);
            }
#pragma unroll
            for (int mt = 0; mt < 2; mt++)
#pragma unroll
                for (int nt = 0; nt < 8; nt++) {
                    mma_bf16(c[mt][nt], ah[mt], bh[nt]);
                    mma_bf16(c[mt][nt], ah[mt], bl[nt]);
                    mma_bf16(c[mt][nt], al[mt], bh[nt]);
                }
        }
    }

    // ---- epilogue: direct stores ----
#pragma unroll
    for (int mt = 0; mt < 2; mt++)
#pragma unroll
        for (int nt = 0; nt < 8; nt++) {
            int row = wid * 32 + mt * 16 + gID;
            int col = n0 + nt * 8 + tig * 2;
            *(float2*)(Cp + (size_t)row * ldc + col) =
                make_float2(c[mt][nt][0], c[mt][nt][1]);
            *(float2*)(Cp + (size_t)(row + 8) * ldc + col) =
                make_float2(c[mt][nt][2], c[mt][nt][3]);
        }
}

// ---- GEMM wrappers ----
__global__ void __launch_bounds__(128)
kg_qkv(const float* __restrict__ Wq, const float* __restrict__ Wk,
       const float* __restrict__ Wv) {
    const float* W = (blockIdx.z == 0) ? Wq : (blockIdx.z == 1) ? Wk : Wv;
    float* Cp = g_part + (size_t)(blockIdx.z * 4 + blockIdx.y) * TnDn;
    gemm_core(g_XNh, g_XNl, Dn, W, Dn, Cp, Dn, blockIdx.y * 256, 4, blockIdx.x * 64);
}
__global__ void __launch_bounds__(128)
kg_wo(const float* __restrict__ Wo) {
    float* Cp = g_part + (size_t)blockIdx.y * TnDn;
    gemm_core(g_Ah, g_Al, Dn, Wo, Dn, Cp, Dn, blockIdx.y * 128, 2, blockIdx.x * 64);
}
__global__ void __launch_bounds__(128)
kg_gu(const float* __restrict__ Wg, const float* __restrict__ Wu) {
    const float* W = (blockIdx.z == 0) ? Wg : Wu;
    float* Cp = g_part + (size_t)(blockIdx.z * 2 + blockIdx.y) * TnFn;
    gemm_core(g_XNh, g_XNl, Dn, W, Fn, Cp, Fn, blockIdx.y * 512, 8, blockIdx.x * 64);
}
__global__ void __launch_bounds__(128)
kg_down(const float* __restrict__ Wd) {
    float* Cp = g_part + (size_t)blockIdx.y * TnDn;
    gemm_core(g_Hh, g_Hl, Fn, Wd, Dn, Cp, Dn, blockIdx.y * 704, 11, blockIdx.x * 64);
}

// ---- elementwise / reductions ----
__device__ __forceinline__ float blockReduceSum(float v) {
    __shared__ float red[32];
    __shared__ float tot;
    int lane = threadIdx.x & 31, warp = threadIdx.x >> 5;
#pragma unroll
    for (int o = 16; o > 0; o >>= 1) v += __shfl_xor_sync(0xffffffffu, v, o);
    if (lane == 0) red[warp] = v;
    __syncthreads();
    int nw = (blockDim.x + 31) >> 5;
    if (warp == 0) {
        float x = (threadIdx.x < nw) ? red[threadIdx.x] : 0.f;
#pragma unroll
        for (int o = 16; o > 0; o >>= 1) x += __shfl_xor_sync(0xffffffffu, x, o);
        if (threadIdx.x == 0) tot = x;
    }
    __syncthreads();
    return tot;
}

__global__ void k_embed(const int* __restrict__ ids, const float* __restrict__ emb) {
    int t = blockIdx.x;
    int row = ids[t];
    const float4* src = (const float4*)(emb + (size_t)row * Dn);
    float4* dst = (float4*)(g_X + (size_t)t * Dn);
    for (int i = threadIdx.x; i < Dn / 4; i += blockDim.x) dst[i] = src[i];
}

// add nparts partials (stride TnDn) into g_X, rmsnorm -> bf16 hi/lo
__global__ void k_addnorm(int nparts, const float* __restrict__ w) {
    int t = blockIdx.x;
    int d4 = threadIdx.x * 4;
    float4 acc = *(const float4*)(g_X + (size_t)t * Dn + d4);
    for (int p = 0; p < nparts; p++) {
        float4 pv = *(const float4*)(g_part + (size_t)p * TnDn + (size_t)t * Dn + d4);
        acc.x += pv.x; acc.y += pv.y; acc.z += pv.z; acc.w += pv.w;
    }
    *(float4*)(g_X + (size_t)t * Dn + d4) = acc;
    float ss = acc.x * acc.x + acc.y * acc.y + acc.z * acc.z + acc.w * acc.w;
    ss = blockReduceSum(ss);
    float inv = rsqrtf(ss / (float)Dn + 1e-5f);
    float4 wv = *(const float4*)(w + d4);
    float xn[4] = { acc.x * inv * wv.x, acc.y * inv * wv.y,
                    acc.z * inv * wv.z, acc.w * inv * wv.w };
#pragma unroll
    for (int i = 0; i < 4; i++) {
        __nv_bfloat16 hh = __float2bfloat16(xn[i]);
        g_XNh[(size_t)t * Dn + d4 + i] = hh;
        g_XNl[(size_t)t * Dn + d4 + i] = __float2bfloat16(xn[i] - __bfloat162float(hh));
    }
}

// QKV split-K reduce (4 each) + RoPE -> fp32. grid=Tn, block=512.
__global__ void k_qkv_rr() {
    int t = blockIdx.x;
    int hh = threadIdx.x >> 5, d = threadIdx.x & 31;
    double invf = pow(10000.0, -(double)d / 32.0);
    double ang = (double)t * invf;
    float c = (float)cos(ang), s = (float)sin(ang);
    int off = t * Dn + hh * DHn + d;
#pragma unroll
    for (int m = 0; m < 3; m++) {
        size_t base = (size_t)(m * 4) * TnDn + off;
        float s0 = 0.f, s1 = 0.f;
#pragma unroll
        for (int p = 0; p < 4; p++) {
            s0 += g_part[base + (size_t)p * TnDn];
            s1 += g_part[base + (size_t)p * TnDn + 32];
        }
        float o0, o1;
        if (m < 2) { o0 = s0 * c - s1 * s; o1 = s1 * c + s0 * s; }
        else       { o0 = s0; o1 = s1; }
        float* dst = (m == 0) ? g_Q : (m == 1) ? g_Kc : g_Vc;
        dst[off] = o0;
        dst[off + 32] = o1;
    }
}

__global__ void k_silu() {
    int i = blockIdx.x * blockDim.x + threadIdx.x;
    float g = g_part[i] + g_part[(size_t)TnFn + i];
    float u = g_part[2 * (size_t)TnFn + i] + g_part[3 * (size_t)TnFn + i];
    float sv = g / (1.f + expf(-g));
    float r = sv * u;
    __nv_bfloat16 hh = __float2bfloat16(r);
    g_Hh[i] = hh;
    g_Hl[i] = __float2bfloat16(r - __bfloat162float(hh));
}

__global__ void k_attn() {
    int i = blockIdx.x, hed = blockIdx.y;
    int tid = threadIdx.x;
    __shared__ float q[DHn];
    __shared__ float KV[Tn][DHn + 1];
    __shared__ float p[Tn];
    __shared__ float rmax[4], rsum[4];

    if (tid < DHn) q[tid] = g_Q[(size_t)i * Dn + hed * DHn + tid];
    for (int idx = tid; idx < Tn * DHn; idx += 128) {
        int r = idx >> 6, c = idx & 63;
        KV[r][c] = g_Kc[(size_t)r * Dn + hed * DHn + c];
    }
    __syncthreads();

    float sc;
    if (tid <= i) {
        float s = 0.f;
#pragma unroll
        for (int d = 0; d < DHn; d++) s = fmaf(q[d], KV[tid][d], s);
        sc = s * 0.125f;
    } else sc = -1e9f;

    float m = sc;
#pragma unroll
    for (int o = 16; o > 0; o >>= 1) m = fmaxf(m, __shfl_xor_sync(0xffffffffu, m, o));
    if ((tid & 31) == 0) rmax[tid >> 5] = m;
    __syncthreads();
    m = fmaxf(fmaxf(rmax[0], rmax[1]), fmaxf(rmax[2], rmax[3]));

    float e = expf(sc - m);
    float s = e;
#pragma unroll
    for (int o = 16; o > 0; o >>= 1) s += __shfl_xor_sync(0xffffffffu, s, o);
    if ((tid & 31) == 0) rsum[tid >> 5] = s;
    __syncthreads();
    s = rsum[0] + rsum[1] + rsum[2] + rsum[3];
    p[tid] = e / s;
    __syncthreads();

    for (int idx = tid; idx < Tn * DHn; idx += 128) {
        int r = idx >> 6, c = idx & 63;
        KV[r][c] = g_Vc[(size_t)r * Dn + hed * DHn + c];
    }
    __syncthreads();

    if (tid < DHn) {
        float o = 0.f;
#pragma unroll 8
        for (int j = 0; j < Tn; j++) o = fmaf(p[j], KV[j][tid], o);
        size_t oi = (size_t)i * Dn + hed * DHn + tid;
        __nv_bfloat16 hh = __float2bfloat16(o);
        g_Ah[oi] = hh;
        g_Al[oi] = __float2bfloat16(o - __bfloat162float(hh));
    }
}

__global__ void k_addX() {
    int i = blockIdx.x * blockDim.x + threadIdx.x;
    g_X[i] += g_part[i] + g_part[(size_t)TnDn + i]
            + g_part[2 * (size_t)TnDn + i] + g_part[3 * (size_t)TnDn + i];
}

__global__ void k_finalnorm(const float* __restrict__ w) {
    const float4* x4 = (const float4*)(g_X + (size_t)(Tn - 1) * Dn);
    const float4* w4 = (const float4*)w;
    float4* o4 = (float4*)g_xl;
    float4 xv = x4[threadIdx.x];
    float ss = xv.x * xv.x + xv.y * xv.y + xv.z * xv.z + xv.w * xv.w;
    ss = blockReduceSum(ss);
    float inv = rsqrtf(ss / (float)Dn + 1e-5f);
    float4 wv = w4[threadIdx.x];
    o4[threadIdx.x] = make_float4(xv.x * inv * wv.x, xv.y * inv * wv.y,
                                  xv.z * inv * wv.z, xv.w * inv * wv.w);
}

__global__ void k_logits(const float* __restrict__ emb, float* __restrict__ out) {
    __shared__ float4 xs[Dn / 4];
    for (int i = threadIdx.x; i < Dn / 4; i += blockDim.x)
        xs[i] = ((const float4*)g_xl)[i];
    __syncthreads();
    int warp = threadIdx.x >> 5, lane = threadIdx.x & 31;
    int row = blockIdx.x * 8 + warp;
    if (row < Vn) {
        const float4* e4 = (const float4*)(emb + (size_t)row * Dn);
        float s = 0.f;
#pragma unroll
        for (int k = lane; k < Dn / 4; k += 32) {
            float4 a = e4[k], b = xs[k];
            s += a.x * b.x + a.y * b.y + a.z * b.z + a.w * b.w;
        }
#pragma unroll
        for (int o = 16; o > 0; o >>= 1) s += __shfl_xor_sync(0xffffffffu, s, o);
        if (lane == 0) out[row] = s;
    }
}

// ---- host ----
extern "C" void kernel_launch(void* const* d_in, const int* in_sizes, int n_in,
                              void* d_out, int out_size) {
    const int*   ids       = (const int*)  d_in[0];
    const float* emb       = (const float*)d_in[1];
    const float* Wq        = (const float*)d_in[2];
    const float* Wk        = (const float*)d_in[3];
    const float* Wv        = (const float*)d_in[4];
    const float* Wo        = (const float*)d_in[5];
    const float* Wg        = (const float*)d_in[6];
    const float* Wu        = (const float*)d_in[7];
    const float* Wd        = (const float*)d_in[8];
    const float* attn_norm = (const float*)d_in[9];
    const float* ffn_norm  = (const float*)d_in[10];
    const float* norm_out  = (const float*)d_in[11];
    float* out = (float*)d_out;

    cudaFuncSetAttribute(kg_qkv,  cudaFuncAttributeMaxDynamicSharedMemorySize, SMEM_BYTES);
    cudaFuncSetAttribute(kg_wo,   cudaFuncAttributeMaxDynamicSharedMemorySize, SMEM_BYTES);
    cudaFuncSetAttribute(kg_gu,   cudaFuncAttributeMaxDynamicSharedMemorySize, SMEM_BYTES);
    cudaFuncSetAttribute(kg_down, cudaFuncAttributeMaxDynamicSharedMemorySize, SMEM_BYTES);

    k_embed<<<Tn, 256>>>(ids, emb);

    for (int l = 0; l < Ln; l++) {
        const float* wq = Wq + (size_t)l * Dn * Dn;
        const float* wk = Wk + (size_t)l * Dn * Dn;
        const float* wv = Wv + (size_t)l * Dn * Dn;
        const float* wo = Wo + (size_t)l * Dn * Dn;
        const float* wg = Wg + (size_t)l * Dn * Fn;
        const float* wu = Wu + (size_t)l * Dn * Fn;
        const float* wd = Wd + (size_t)l * Fn * Dn;

        k_addnorm<<<Tn, 256>>>(l == 0 ? 0 : 4, attn_norm + (size_t)l * Dn);
        kg_qkv<<<dim3(16, 4, 3), 128, SMEM_BYTES>>>(wq, wk, wv);
        k_qkv_rr<<<Tn, 512>>>();
        k_attn<<<dim3(Tn, Hn), 128>>>();
        kg_wo<<<dim3(16, 8), 128, SMEM_BYTES>>>(wo);
        k_addnorm<<<Tn, 256>>>(8, ffn_norm + (size_t)l * Dn);
        kg_gu<<<dim3(44, 2, 2), 128, SMEM_BYTES>>>(wg, wu);
        k_silu<<<TnFn / 256, 256>>>();
        kg_down<<<dim3(16, 4), 128, SMEM_BYTES>>>(wd);
    }

    k_addX<<<TnDn / 256, 256>>>();
    k_finalnorm<<<1, 256>>>(norm_out);
    k_logits<<<(Vn + 7) / 8, 256>>>(emb, out);
}

// round 8
// speedup vs baseline: 1.6239x; 1.1817x over previous
#include <cuda_runtime.h>
#include <cuda_bf16.h>
#include <math.h>
#include <stdint.h>

#define Tn  128
#define Dn  1024
#define Ln  8
#define Hn  16
#define Fn  2816
#define DHn 64
#define Vn  32000
#define TnDn (Tn*Dn)
#define TnFn (Tn*Fn)

// ---- scratch ----
__device__ float g_X [TnDn];
__device__ float g_Q [TnDn];
__device__ float g_Kc[TnDn];
__device__ float g_Vc[TnDn];
__device__ float g_part[12 * TnDn];
__device__ float g_xl[Dn];
__device__ __nv_bfloat16 g_XNh[TnDn], g_XNl[TnDn];
__device__ __nv_bfloat16 g_Ah [TnDn], g_Al [TnDn];
__device__ __nv_bfloat16 g_Hh [TnFn], g_Hl [TnFn];

// ---- helpers ----
__device__ __forceinline__ uint32_t smem_u32(const void* p) {
    uint32_t a;
    asm("{ .reg .u64 t; cvta.to.shared.u64 t, %1; cvt.u32.u64 %0, t; }" : "=r"(a) : "l"(p));
    return a;
}
#define LDSM_X4(r0, r1, r2, r3, a) \
    asm volatile("ldmatrix.sync.aligned.m8n8.x4.shared.b16 {%0,%1,%2,%3}, [%4];" \
                 : "=r"(r0), "=r"(r1), "=r"(r2), "=r"(r3) : "r"(a))

__device__ __forceinline__ void mma_bf16(float* d, const uint32_t* a, const uint32_t* b) {
    asm volatile("mma.sync.aligned.m16n8k16.row.col.f32.bf16.bf16.f32 "
                 "{%0,%1,%2,%3}, {%4,%5,%6,%7}, {%8,%9}, {%0,%1,%2,%3};"
                 : "+f"(d[0]), "+f"(d[1]), "+f"(d[2]), "+f"(d[3])
                 : "r"(a[0]), "r"(a[1]), "r"(a[2]), "r"(a[3]), "r"(b[0]), "r"(b[1]));
}
__device__ __forceinline__ void cp16(uint32_t dst, const void* src) {
    asm volatile("cp.async.cg.shared.global [%0], [%1], 16;" :: "r"(dst), "l"(src));
}
#define CP_COMMIT() asm volatile("cp.async.commit_group;")
#define CP_WAIT0()  asm volatile("cp.async.wait_group 0;")

// ---- GEMM core: C_tile[128 x 64] = Ahl[128,K] * W[K, n0..n0+64), hi/lo bf16 ----
// Double-buffered smem, pitch 72 bf16 (144B) rows.
#define PITCHB 144
#define SM_AH(s) ((s) * 18432)
#define SM_AL(s) (36864 + (s) * 18432)
#define SM_BH(s) (73728 + (s) * 9216)
#define SM_BL(s) (92160 + (s) * 9216)
#define SMEM_BYTES 110592

__device__ void gemm_core(const __nv_bfloat16* __restrict__ Ah,
                          const __nv_bfloat16* __restrict__ Al, int lda,
                          const float* __restrict__ B, int ldb,
                          float* __restrict__ Cp, int ldc,
                          int k0, int nkb, int n0)
{
    extern __shared__ unsigned char sm[];
    const uint32_t smb = smem_u32(sm);
    const int tid = threadIdx.x, wid = tid >> 5, lane = tid & 31;
    const int gID = lane >> 2, tig = lane & 3;

    float c[2][8][4];
#pragma unroll
    for (int mt = 0; mt < 2; mt++)
#pragma unroll
        for (int nt = 0; nt < 8; nt++)
#pragma unroll
            for (int i = 0; i < 4; i++) c[mt][nt][i] = 0.f;

    const int bkk0 = (tid & 7) << 3;   // B: 8-k subgroup
    const int bn4  = (tid >> 3) << 2;  // B: 4 consecutive n
    const int a_m  = tid >> 3;         // A row per chunk base (j*16 added below)
    const int a_k8 = (tid & 7) << 3;   // A k offset
    const int a_r = lane & 15, a_h = lane >> 4;
    const int b_nr = ((lane >> 4) << 3) | (lane & 7);
    const int b_kh = (lane >> 3) & 1;

    // ---- prologue: A(0) via cp.async, B(0) into regs ----
    {
        const int kc = k0;
#pragma unroll
        for (int j = 0; j < 8; j++) {
            int m = a_m + j * 16;
            uint32_t off = (uint32_t)m * PITCHB + a_k8 * 2;
            cp16(smb + SM_AH(0) + off, Ah + (size_t)m * lda + kc + a_k8);
            cp16(smb + SM_AL(0) + off, Al + (size_t)m * lda + kc + a_k8);
        }
        CP_COMMIT();
    }
    float4 f[8];
#pragma unroll
    for (int j = 0; j < 8; j++)
        f[j] = *(const float4*)(B + (size_t)(k0 + bkk0 + j) * ldb + n0 + bn4);

    for (int it = 0; it < nkb; ++it) {
        const int buf = it & 1;
        const int kc = k0 + it * 64;

        // convert current B regs -> smem(buf), hi/lo
#pragma unroll
        for (int i = 0; i < 4; i++) {
            union { __nv_bfloat16 b[8]; uint4 v; } hb, lb;
#pragma unroll
            for (int j = 0; j < 8; j++) {
                float x = (i == 0) ? f[j].x : (i == 1) ? f[j].y : (i == 2) ? f[j].z : f[j].w;
                __nv_bfloat16 hh = __float2bfloat16(x);
                hb.b[j] = hh;
                lb.b[j] = __float2bfloat16(x - __bfloat162float(hh));
            }
            uint32_t off = (uint32_t)(bn4 + i) * PITCHB + bkk0 * 2;
            *(uint4*)(sm + SM_BH(buf) + off) = hb.v;
            *(uint4*)(sm + SM_BL(buf) + off) = lb.v;
        }
        CP_WAIT0();
        __syncthreads();

        // prefetch next iteration (A cp.async + B LDGs) before compute
        if (it + 1 < nkb) {
            const int kn = kc + 64;
#pragma unroll
            for (int j = 0; j < 8; j++) {
                int m = a_m + j * 16;
                uint32_t off = (uint32_t)m * PITCHB + a_k8 * 2;
                cp16(smb + SM_AH(buf ^ 1) + off, Ah + (size_t)m * lda + kn + a_k8);
                cp16(smb + SM_AL(buf ^ 1) + off, Al + (size_t)m * lda + kn + a_k8);
            }
            CP_COMMIT();
#pragma unroll
            for (int j = 0; j < 8; j++)
                f[j] = *(const float4*)(B + (size_t)(kn + bkk0 + j) * ldb + n0 + bn4);
        }

        // ---- compute 4 k-steps of 16 from smem(buf) ----
        const uint32_t aH = smb + SM_AH(buf), aL = smb + SM_AL(buf);
        const uint32_t bH = smb + SM_BH(buf), bL = smb + SM_BL(buf);
#pragma unroll
        for (int s = 0; s < 4; s++) {
            uint32_t ah[2][4], al[2][4], bh[8][2], bl[8][2];
#pragma unroll
            for (int mt = 0; mt < 2; mt++) {
                uint32_t ao = (uint32_t)(wid * 32 + mt * 16 + a_r) * PITCHB
                            + (s * 16 + a_h * 8) * 2;
                LDSM_X4(ah[mt][0], ah[mt][1], ah[mt][2], ah[mt][3], aH + ao);
                LDSM_X4(al[mt][0], al[mt][1], al[mt][2], al[mt][3], aL + ao);
            }
#pragma unroll
            for (int np = 0; np < 4; np++) {
                uint32_t bo = (uint32_t)(np * 16 + b_nr) * PITCHB
                            + (s * 16 + b_kh * 8) * 2;
                LDSM_X4(bh[np*2][0], bh[np*2][1], bh[np*2+1][0], bh[np*2+1][1], bH + bo);
                LDSM_X4(bl[np*2][0], bl[np*2][1], bl[np*2+1][0], bl[np*2+1][1], bL + bo);
            }
#pragma unroll
            for (int mt = 0; mt < 2; mt++)
#pragma unroll
                for (int nt = 0; nt < 8; nt++) {
                    mma_bf16(c[mt][nt], ah[mt], bh[nt]);
                    mma_bf16(c[mt][nt], ah[mt], bl[nt]);
                    mma_bf16(c[mt][nt], al[mt], bh[nt]);
                }
        }
    }

    // ---- epilogue: direct stores ----
#pragma unroll
    for (int mt = 0; mt < 2; mt++)
#pragma unroll
        for (int nt = 0; nt < 8; nt++) {
            int row = wid * 32 + mt * 16 + gID;
            int col = n0 + nt * 8 + tig * 2;
            *(float2*)(Cp + (size_t)row * ldc + col) =
                make_float2(c[mt][nt][0], c[mt][nt][1]);
            *(float2*)(Cp + (size_t)(row + 8) * ldc + col) =
                make_float2(c[mt][nt][2], c[mt][nt][3]);
        }
}

// ---- GEMM wrappers ----
__global__ void __launch_bounds__(128)
kg_qkv(const float* __restrict__ Wq, const float* __restrict__ Wk,
       const float* __restrict__ Wv) {
    const float* W = (blockIdx.z == 0) ? Wq : (blockIdx.z == 1) ? Wk : Wv;
    float* Cp = g_part + (size_t)(blockIdx.z * 4 + blockIdx.y) * TnDn;
    gemm_core(g_XNh, g_XNl, Dn, W, Dn, Cp, Dn, blockIdx.y * 256, 4, blockIdx.x * 64);
}
__global__ void __launch_bounds__(128)
kg_wo(const float* __restrict__ Wo) {
    float* Cp = g_part + (size_t)blockIdx.y * TnDn;
    gemm_core(g_Ah, g_Al, Dn, Wo, Dn, Cp, Dn, blockIdx.y * 128, 2, blockIdx.x * 64);
}
__global__ void __launch_bounds__(128)
kg_gu(const float* __restrict__ Wg, const float* __restrict__ Wu) {
    const float* W = (blockIdx.z == 0) ? Wg : Wu;
    float* Cp = g_part + (size_t)(blockIdx.z * 2 + blockIdx.y) * TnFn;
    gemm_core(g_XNh, g_XNl, Dn, W, Fn, Cp, Fn, blockIdx.y * 512, 8, blockIdx.x * 64);
}
__global__ void __launch_bounds__(128)
kg_down(const float* __restrict__ Wd) {
    float* Cp = g_part + (size_t)blockIdx.y * TnDn;
    gemm_core(g_Hh, g_Hl, Fn, Wd, Dn, Cp, Dn, blockIdx.y * 256, 4, blockIdx.x * 64);
}

// ---- elementwise / reductions ----
__device__ __forceinline__ float blockReduceSum(float v) {
    __shared__ float red[32];
    __shared__ float tot;
    int lane = threadIdx.x & 31, warp = threadIdx.x >> 5;
#pragma unroll
    for (int o = 16; o > 0; o >>= 1) v += __shfl_xor_sync(0xffffffffu, v, o);
    if (lane == 0) red[warp] = v;
    __syncthreads();
    int nw = (blockDim.x + 31) >> 5;
    if (warp == 0) {
        float x = (threadIdx.x < nw) ? red[threadIdx.x] : 0.f;
#pragma unroll
        for (int o = 16; o > 0; o >>= 1) x += __shfl_xor_sync(0xffffffffu, x, o);
        if (threadIdx.x == 0) tot = x;
    }
    __syncthreads();
    return tot;
}

__global__ void k_embed(const int* __restrict__ ids, const float* __restrict__ emb) {
    int t = blockIdx.x;
    int row = ids[t];
    const float4* src = (const float4*)(emb + (size_t)row * Dn);
    float4* dst = (float4*)(g_X + (size_t)t * Dn);
    for (int i = threadIdx.x; i < Dn / 4; i += blockDim.x) dst[i] = src[i];
}

// add nparts partials (stride TnDn) into g_X, rmsnorm -> bf16 hi/lo
__global__ void k_addnorm(int nparts, const float* __restrict__ w) {
    int t = blockIdx.x;
    int d4 = threadIdx.x * 4;
    float4 acc = *(const float4*)(g_X + (size_t)t * Dn + d4);
    for (int p = 0; p < nparts; p++) {
        float4 pv = *(const float4*)(g_part + (size_t)p * TnDn + (size_t)t * Dn + d4);
        acc.x += pv.x; acc.y += pv.y; acc.z += pv.z; acc.w += pv.w;
    }
    *(float4*)(g_X + (size_t)t * Dn + d4) = acc;
    float ss = acc.x * acc.x + acc.y * acc.y + acc.z * acc.z + acc.w * acc.w;
    ss = blockReduceSum(ss);
    float inv = rsqrtf(ss / (float)Dn + 1e-5f);
    float4 wv = *(const float4*)(w + d4);
    float xn[4] = { acc.x * inv * wv.x, acc.y * inv * wv.y,
                    acc.z * inv * wv.z, acc.w * inv * wv.w };
#pragma unroll
    for (int i = 0; i < 4; i++) {
        __nv_bfloat16 hh = __float2bfloat16(xn[i]);
        g_XNh[(size_t)t * Dn + d4 + i] = hh;
        g_XNl[(size_t)t * Dn + d4 + i] = __float2bfloat16(xn[i] - __bfloat162float(hh));
    }
}

// QKV split-K reduce (4 each) + RoPE -> fp32. grid=Tn, block=512.
__global__ void k_qkv_rr() {
    int t = blockIdx.x;
    int hh = threadIdx.x >> 5, d = threadIdx.x & 31;
    double invf = pow(10000.0, -(double)d / 32.0);
    double ang = (double)t * invf;
    float c = (float)cos(ang), s = (float)sin(ang);
    int off = t * Dn + hh * DHn + d;
#pragma unroll
    for (int m = 0; m < 3; m++) {
        size_t base = (size_t)(m * 4) * TnDn + off;
        float s0 = 0.f, s1 = 0.f;
#pragma unroll
        for (int p = 0; p < 4; p++) {
            s0 += g_part[base + (size_t)p * TnDn];
            s1 += g_part[base + (size_t)p * TnDn + 32];
        }
        float o0, o1;
        if (m < 2) { o0 = s0 * c - s1 * s; o1 = s1 * c + s0 * s; }
        else       { o0 = s0; o1 = s1; }
        float* dst = (m == 0) ? g_Q : (m == 1) ? g_Kc : g_Vc;
        dst[off] = o0;
        dst[off + 32] = o1;
    }
}

__global__ void k_silu() {
    int i = blockIdx.x * blockDim.x + threadIdx.x;
    float g = g_part[i] + g_part[(size_t)TnFn + i];
    float u = g_part[2 * (size_t)TnFn + i] + g_part[3 * (size_t)TnFn + i];
    float sv = g / (1.f + expf(-g));
    float r = sv * u;
    __nv_bfloat16 hh = __float2bfloat16(r);
    g_Hh[i] = hh;
    g_Hl[i] = __float2bfloat16(r - __bfloat162float(hh));
}

__global__ void k_attn() {
    int i = blockIdx.x, hed = blockIdx.y;
    int tid = threadIdx.x;
    __shared__ float q[DHn];
    __shared__ float KV[Tn][DHn + 1];
    __shared__ float p[Tn];
    __shared__ float rmax[4], rsum[4];

    if (tid < DHn) q[tid] = g_Q[(size_t)i * Dn + hed * DHn + tid];
    for (int idx = tid; idx < Tn * DHn; idx += 128) {
        int r = idx >> 6, c = idx & 63;
        KV[r][c] = g_Kc[(size_t)r * Dn + hed * DHn + c];
    }
    __syncthreads();

    float sc;
    if (tid <= i) {
        float s = 0.f;
#pragma unroll
        for (int d = 0; d < DHn; d++) s = fmaf(q[d], KV[tid][d], s);
        sc = s * 0.125f;
    } else sc = -1e9f;

    float m = sc;
#pragma unroll
    for (int o = 16; o > 0; o >>= 1) m = fmaxf(m, __shfl_xor_sync(0xffffffffu, m, o));
    if ((tid & 31) == 0) rmax[tid >> 5] = m;
    __syncthreads();
    m = fmaxf(fmaxf(rmax[0], rmax[1]), fmaxf(rmax[2], rmax[3]));

    float e = expf(sc - m);
    float s = e;
#pragma unroll
    for (int o = 16; o > 0; o >>= 1) s += __shfl_xor_sync(0xffffffffu, s, o);
    if ((tid & 31) == 0) rsum[tid >> 5] = s;
    __syncthreads();
    s = rsum[0] + rsum[1] + rsum[2] + rsum[3];
    p[tid] = e / s;
    __syncthreads();

    for (int idx = tid; idx < Tn * DHn; idx += 128) {
        int r = idx >> 6, c = idx & 63;
        KV[r][c] = g_Vc[(size_t)r * Dn + hed * DHn + c];
    }
    __syncthreads();

    if (tid < DHn) {
        float o = 0.f;
#pragma unroll 8
        for (int j = 0; j < Tn; j++) o = fmaf(p[j], KV[j][tid], o);
        size_t oi = (size_t)i * Dn + hed * DHn + tid;
        __nv_bfloat16 hh = __float2bfloat16(o);
        g_Ah[oi] = hh;
        g_Al[oi] = __float2bfloat16(o - __bfloat162float(hh));
    }
}

__global__ void k_addX(int nparts) {
    int i = blockIdx.x * blockDim.x + threadIdx.x;
    float a = 0.f;
    for (int p = 0; p < nparts; p++) a += g_part[(size_t)p * TnDn + i];
    g_X[i] += a;
}

__global__ void k_finalnorm(const float* __restrict__ w) {
    const float4* x4 = (const float4*)(g_X + (size_t)(Tn - 1) * Dn);
    const float4* w4 = (const float4*)w;
    float4* o4 = (float4*)g_xl;
    float4 xv = x4[threadIdx.x];
    float ss = xv.x * xv.x + xv.y * xv.y + xv.z * xv.z + xv.w * xv.w;
    ss = blockReduceSum(ss);
    float inv = rsqrtf(ss / (float)Dn + 1e-5f);
    float4 wv = w4[threadIdx.x];
    o4[threadIdx.x] = make_float4(xv.x * inv * wv.x, xv.y * inv * wv.y,
                                  xv.z * inv * wv.z, xv.w * inv * wv.w);
}

__global__ void k_logits(const float* __restrict__ emb, float* __restrict__ out) {
    __shared__ float4 xs[Dn / 4];
    for (int i = threadIdx.x; i < Dn / 4; i += blockDim.x)
        xs[i] = ((const float4*)g_xl)[i];
    __syncthreads();
    int warp = threadIdx.x >> 5, lane = threadIdx.x & 31;
    int row = blockIdx.x * 8 + warp;
    if (row < Vn) {
        const float4* e4 = (const float4*)(emb + (size_t)row * Dn);
        float s = 0.f;
#pragma unroll
        for (int k = lane; k < Dn / 4; k += 32) {
            float4 a = e4[k], b = xs[k];
            s += a.x * b.x + a.y * b.y + a.z * b.z + a.w * b.w;
        }
#pragma unroll
        for (int o = 16; o > 0; o >>= 1) s += __shfl_xor_sync(0xffffffffu, s, o);
        if (lane == 0) out[row] = s;
    }
}

// ---- host ----
extern "C" void kernel_launch(void* const* d_in, const int* in_sizes, int n_in,
                              void* d_out, int out_size) {
    const int*   ids       = (const int*)  d_in[0];
    const float* emb       = (const float*)d_in[1];
    const float* Wq        = (const float*)d_in[2];
    const float* Wk        = (const float*)d_in[3];
    const float* Wv        = (const float*)d_in[4];
    const float* Wo        = (const float*)d_in[5];
    const float* Wg        = (const float*)d_in[6];
    const float* Wu        = (const float*)d_in[7];
    const float* Wd        = (const float*)d_in[8];
    const float* attn_norm = (const float*)d_in[9];
    const float* ffn_norm  = (const float*)d_in[10];
    const float* norm_out  = (const float*)d_in[11];
    float* out = (float*)d_out;

    cudaFuncSetAttribute(kg_qkv,  cudaFuncAttributeMaxDynamicSharedMemorySize, SMEM_BYTES);
    cudaFuncSetAttribute(kg_wo,   cudaFuncAttributeMaxDynamicSharedMemorySize, SMEM_BYTES);
    cudaFuncSetAttribute(kg_gu,   cudaFuncAttributeMaxDynamicSharedMemorySize, SMEM_BYTES);
    cudaFuncSetAttribute(kg_down, cudaFuncAttributeMaxDynamicSharedMemorySize, SMEM_BYTES);

    k_embed<<<Tn, 256>>>(ids, emb);

    for (int l = 0; l < Ln; l++) {
        const float* wq = Wq + (size_t)l * Dn * Dn;
        const float* wk = Wk + (size_t)l * Dn * Dn;
        const float* wv = Wv + (size_t)l * Dn * Dn;
        const float* wo = Wo + (size_t)l * Dn * Dn;
        const float* wg = Wg + (size_t)l * Dn * Fn;
        const float* wu = Wu + (size_t)l * Dn * Fn;
        const float* wd = Wd + (size_t)l * Fn * Dn;

        k_addnorm<<<Tn, 256>>>(l == 0 ? 0 : 11, attn_norm + (size_t)l * Dn);
        kg_qkv<<<dim3(16, 4, 3), 128, SMEM_BYTES>>>(wq, wk, wv);
        k_qkv_rr<<<Tn, 512>>>();
        k_attn<<<dim3(Tn, Hn), 128>>>();
        kg_wo<<<dim3(16, 8), 128, SMEM_BYTES>>>(wo);
        k_addnorm<<<Tn, 256>>>(8, ffn_norm + (size_t)l * Dn);
        kg_gu<<<dim3(44, 2, 2), 128, SMEM_BYTES>>>(wg, wu);
        k_silu<<<TnFn / 256, 256>>>();
        kg_down<<<dim3(16, 11), 128, SMEM_BYTES>>>(wd);
    }

    k_addX<<<TnDn / 256, 256>>>(11);
    k_finalnorm<<<1, 256>>>(norm_out);
    k_logits<<<(Vn + 7) / 8, 256>>>(emb, out);
}

// round 13
// speedup vs baseline: 1.6301x; 1.0038x over previous
#include <cuda_runtime.h>
#include <cuda_bf16.h>
#include <math.h>
#include <stdint.h>

#define Tn  128
#define Dn  1024
#define Ln  8
#define Hn  16
#define Fn  2816
#define DHn 64
#define Vn  32000
#define TnDn (Tn*Dn)
#define TnFn (Tn*Fn)

// ---- scratch ----
__device__ float g_X [TnDn];
__device__ float g_Q [TnDn];
__device__ float g_Kc[TnDn];
__device__ float g_Vc[TnDn];
__device__ float g_part[12 * TnDn];
__device__ float g_xl[Dn];
__device__ float g_tmp[12288];                 // last-layer GEMV vectors
__device__ __nv_bfloat16 g_XNh[TnDn], g_XNl[TnDn];
__device__ __nv_bfloat16 g_Ah [TnDn], g_Al [TnDn];
__device__ __nv_bfloat16 g_Hh [TnFn], g_Hl [TnFn];
__device__ __nv_bfloat16 g_hrh[Fn], g_hrl[Fn]; // last-layer silu row

// ---- helpers ----
__device__ __forceinline__ uint32_t smem_u32(const void* p) {
    uint32_t a;
    asm("{ .reg .u64 t; cvta.to.shared.u64 t, %1; cvt.u32.u64 %0, t; }" : "=r"(a) : "l"(p));
    return a;
}
#define LDSM_X4(r0, r1, r2, r3, a) \
    asm volatile("ldmatrix.sync.aligned.m8n8.x4.shared.b16 {%0,%1,%2,%3}, [%4];" \
                 : "=r"(r0), "=r"(r1), "=r"(r2), "=r"(r3) : "r"(a))

__device__ __forceinline__ void mma_bf16(float* d, const uint32_t* a, const uint32_t* b) {
    asm volatile("mma.sync.aligned.m16n8k16.row.col.f32.bf16.bf16.f32 "
                 "{%0,%1,%2,%3}, {%4,%5,%6,%7}, {%8,%9}, {%0,%1,%2,%3};"
                 : "+f"(d[0]), "+f"(d[1]), "+f"(d[2]), "+f"(d[3])
                 : "r"(a[0]), "r"(a[1]), "r"(a[2]), "r"(a[3]), "r"(b[0]), "r"(b[1]));
}
__device__ __forceinline__ void cp16(uint32_t dst, const void* src) {
    asm volatile("cp.async.cg.shared.global [%0], [%1], 16;" :: "r"(dst), "l"(src));
}
#define CP_COMMIT() asm volatile("cp.async.commit_group;")
#define CP_WAIT0()  asm volatile("cp.async.wait_group 0;")

// ---- GEMM core (byte-identical to passing r8) ----
#define PITCHB 144
#define SM_AH(s) ((s) * 18432)
#define SM_AL(s) (36864 + (s) * 18432)
#define SM_BH(s) (73728 + (s) * 9216)
#define SM_BL(s) (92160 + (s) * 9216)
#define SMEM_BYTES 110592

__device__ void gemm_core(const __nv_bfloat16* __restrict__ Ah,
                          const __nv_bfloat16* __restrict__ Al, int lda,
                          const float* __restrict__ B, int ldb,
                          float* __restrict__ Cp, int ldc,
                          int k0, int nkb, int n0)
{
    extern __shared__ unsigned char sm[];
    const uint32_t smb = smem_u32(sm);
    const int tid = threadIdx.x, wid = tid >> 5, lane = tid & 31;
    const int gID = lane >> 2, tig = lane & 3;

    float c[2][8][4];
#pragma unroll
    for (int mt = 0; mt < 2; mt++)
#pragma unroll
        for (int nt = 0; nt < 8; nt++)
#pragma unroll
            for (int i = 0; i < 4; i++) c[mt][nt][i] = 0.f;

    const int bkk0 = (tid & 7) << 3;
    const int bn4  = (tid >> 3) << 2;
    const int a_m  = tid >> 3;
    const int a_k8 = (tid & 7) << 3;
    const int a_r = lane & 15, a_h = lane >> 4;
    const int b_nr = ((lane >> 4) << 3) | (lane & 7);
    const int b_kh = (lane >> 3) & 1;

    {
        const int kc = k0;
#pragma unroll
        for (int j = 0; j < 8; j++) {
            int m = a_m + j * 16;
            uint32_t off = (uint32_t)m * PITCHB + a_k8 * 2;
            cp16(smb + SM_AH(0) + off, Ah + (size_t)m * lda + kc + a_k8);
            cp16(smb + SM_AL(0) + off, Al + (size_t)m * lda + kc + a_k8);
        }
        CP_COMMIT();
    }
    float4 f[8];
#pragma unroll
    for (int j = 0; j < 8; j++)
        f[j] = *(const float4*)(B + (size_t)(k0 + bkk0 + j) * ldb + n0 + bn4);

    for (int it = 0; it < nkb; ++it) {
        const int buf = it & 1;
        const int kc = k0 + it * 64;

#pragma unroll
        for (int i = 0; i < 4; i++) {
            union { __nv_bfloat16 b[8]; uint4 v; } hb, lb;
#pragma unroll
            for (int j = 0; j < 8; j++) {
                float x = (i == 0) ? f[j].x : (i == 1) ? f[j].y : (i == 2) ? f[j].z : f[j].w;
                __nv_bfloat16 hh = __float2bfloat16(x);
                hb.b[j] = hh;
                lb.b[j] = __float2bfloat16(x - __bfloat162float(hh));
            }
            uint32_t off = (uint32_t)(bn4 + i) * PITCHB + bkk0 * 2;
            *(uint4*)(sm + SM_BH(buf) + off) = hb.v;
            *(uint4*)(sm + SM_BL(buf) + off) = lb.v;
        }
        CP_WAIT0();
        __syncthreads();

        if (it + 1 < nkb) {
            const int kn = kc + 64;
#pragma unroll
            for (int j = 0; j < 8; j++) {
                int m = a_m + j * 16;
                uint32_t off = (uint32_t)m * PITCHB + a_k8 * 2;
                cp16(smb + SM_AH(buf ^ 1) + off, Ah + (size_t)m * lda + kn + a_k8);
                cp16(smb + SM_AL(buf ^ 1) + off, Al + (size_t)m * lda + kn + a_k8);
            }
            CP_COMMIT();
#pragma unroll
            for (int j = 0; j < 8; j++)
                f[j] = *(const float4*)(B + (size_t)(kn + bkk0 + j) * ldb + n0 + bn4);
        }

        const uint32_t aH = smb + SM_AH(buf), aL = smb + SM_AL(buf);
        const uint32_t bH = smb + SM_BH(buf), bL = smb + SM_BL(buf);
#pragma unroll
        for (int s = 0; s < 4; s++) {
            uint32_t ah[2][4], al[2][4], bh[8][2], bl[8][2];
#pragma unroll
            for (int mt = 0; mt < 2; mt++) {
                uint32_t ao = (uint32_t)(wid * 32 + mt * 16 + a_r) * PITCHB
                            + (s * 16 + a_h * 8) * 2;
                LDSM_X4(ah[mt][0], ah[mt][1], ah[mt][2], ah[mt][3], aH + ao);
                LDSM_X4(al[mt][0], al[mt][1], al[mt][2], al[mt][3], aL + ao);
            }
#pragma unroll
            for (int np = 0; np < 4; np++) {
                uint32_t bo = (uint32_t)(np * 16 + b_nr) * PITCHB
                            + (s * 16 + b_kh * 8) * 2;
                LDSM_X4(bh[np*2][0], bh[np*2][1], bh[np*2+1][0], bh[np*2+1][1], bH + bo);
                LDSM_X4(bl[np*2][0], bl[np*2][1], bl[np*2+1][0], bl[np*2+1][1], bL + bo);
            }
#pragma unroll
            for (int mt = 0; mt < 2; mt++)
#pragma unroll
                for (int nt = 0; nt < 8; nt++) {
                    mma_bf16(c[mt][nt], ah[mt], bh[nt]);
                    mma_bf16(c[mt][nt], ah[mt], bl[nt]);
                    mma_bf16(c[mt][nt], al[mt], bh[nt]);
                }
        }
    }

#pragma unroll
    for (int mt = 0; mt < 2; mt++)
#pragma unroll
        for (int nt = 0; nt < 8; nt++) {
            int row = wid * 32 + mt * 16 + gID;
            int col = n0 + nt * 8 + tig * 2;
            *(float2*)(Cp + (size_t)row * ldc + col) =
                make_float2(c[mt][nt][0], c[mt][nt][1]);
            *(float2*)(Cp + (size_t)(row + 8) * ldc + col) =
                make_float2(c[mt][nt][2], c[mt][nt][3]);
        }
}

// ---- GEMM wrappers ----
__global__ void __launch_bounds__(128)
kg_qkv(const float* __restrict__ Wq, const float* __restrict__ Wk,
       const float* __restrict__ Wv) {
    const float* W = (blockIdx.z == 0) ? Wq : (blockIdx.z == 1) ? Wk : Wv;
    float* Cp = g_part + (size_t)(blockIdx.z * 4 + blockIdx.y) * TnDn;
    gemm_core(g_XNh, g_XNl, Dn, W, Dn, Cp, Dn, blockIdx.y * 256, 4, blockIdx.x * 64);
}
__global__ void __launch_bounds__(128)
kg_wo(const float* __restrict__ Wo) {
    float* Cp = g_part + (size_t)blockIdx.y * TnDn;
    gemm_core(g_Ah, g_Al, Dn, Wo, Dn, Cp, Dn, blockIdx.y * 128, 2, blockIdx.x * 64);
}
__global__ void __launch_bounds__(128)
kg_gu(const float* __restrict__ Wg, const float* __restrict__ Wu) {
    const float* W = (blockIdx.z == 0) ? Wg : Wu;
    float* Cp = g_part + (size_t)(blockIdx.z * 2 + blockIdx.y) * TnFn;
    gemm_core(g_XNh, g_XNl, Dn, W, Fn, Cp, Fn, blockIdx.y * 512, 8, blockIdx.x * 64);
}
__global__ void __launch_bounds__(128)
kg_down(const float* __restrict__ Wd) {
    float* Cp = g_part + (size_t)blockIdx.y * TnDn;
    gemm_core(g_Hh, g_Hl, Fn, Wd, Dn, Cp, Dn, blockIdx.y * 256, 4, blockIdx.x * 64);
}

// ---- elementwise / reductions ----
__device__ __forceinline__ float blockReduceSum(float v) {
    __shared__ float red[32];
    __shared__ float tot;
    int lane = threadIdx.x & 31, warp = threadIdx.x >> 5;
#pragma unroll
    for (int o = 16; o > 0; o >>= 1) v += __shfl_xor_sync(0xffffffffu, v, o);
    if (lane == 0) red[warp] = v;
    __syncthreads();
    int nw = (blockDim.x + 31) >> 5;
    if (warp == 0) {
        float x = (threadIdx.x < nw) ? red[threadIdx.x] : 0.f;
#pragma unroll
        for (int o = 16; o > 0; o >>= 1) x += __shfl_xor_sync(0xffffffffu, x, o);
        if (threadIdx.x == 0) tot = x;
    }
    __syncthreads();
    return tot;
}

__global__ void k_embed(const int* __restrict__ ids, const float* __restrict__ emb) {
    int t = blockIdx.x;
    int row = ids[t];
    const float4* src = (const float4*)(emb + (size_t)row * Dn);
    float4* dst = (float4*)(g_X + (size_t)t * Dn);
    for (int i = threadIdx.x; i < Dn / 4; i += blockDim.x) dst[i] = src[i];
}

__global__ void k_addnorm(int nparts, const float* __restrict__ w) {
    int t = blockIdx.x;
    int d4 = threadIdx.x * 4;
    float4 acc = *(const float4*)(g_X + (size_t)t * Dn + d4);
    for (int p = 0; p < nparts; p++) {
        float4 pv = *(const float4*)(g_part + (size_t)p * TnDn + (size_t)t * Dn + d4);
        acc.x += pv.x; acc.y += pv.y; acc.z += pv.z; acc.w += pv.w;
    }
    *(float4*)(g_X + (size_t)t * Dn + d4) = acc;
    float ss = acc.x * acc.x + acc.y * acc.y + acc.z * acc.z + acc.w * acc.w;
    ss = blockReduceSum(ss);
    float inv = rsqrtf(ss / (float)Dn + 1e-5f);
    float4 wv = *(const float4*)(w + d4);
    float xn[4] = { acc.x * inv * wv.x, acc.y * inv * wv.y,
                    acc.z * inv * wv.z, acc.w * inv * wv.w };
#pragma unroll
    for (int i = 0; i < 4; i++) {
        __nv_bfloat16 hh = __float2bfloat16(xn[i]);
        g_XNh[(size_t)t * Dn + d4 + i] = hh;
        g_XNl[(size_t)t * Dn + d4 + i] = __float2bfloat16(xn[i] - __bfloat162float(hh));
    }
}

// QKV split-K reduce (4 each) + RoPE -> fp32. grid=Tn, block=512.  (r8-identical)
__global__ void k_qkv_rr() {
    int t = blockIdx.x;
    int hh = threadIdx.x >> 5, d = threadIdx.x & 31;
    double invf = pow(10000.0, -(double)d / 32.0);
    double ang = (double)t * invf;
    float c = (float)cos(ang), s = (float)sin(ang);
    int off = t * Dn + hh * DHn + d;
#pragma unroll
    for (int m = 0; m < 3; m++) {
        size_t base = (size_t)(m * 4) * TnDn + off;
        float s0 = 0.f, s1 = 0.f;
#pragma unroll
        for (int p = 0; p < 4; p++) {
            s0 += g_part[base + (size_t)p * TnDn];
            s1 += g_part[base + (size_t)p * TnDn + 32];
        }
        float o0, o1;
        if (m < 2) { o0 = s0 * c - s1 * s; o1 = s1 * c + s0 * s; }
        else       { o0 = s0; o1 = s1; }
        float* dst = (m == 0) ? g_Q : (m == 1) ? g_Kc : g_Vc;
        dst[off] = o0;
        dst[off + 32] = o1;
    }
}

__global__ void k_silu() {
    int i = blockIdx.x * blockDim.x + threadIdx.x;
    float g = g_part[i] + g_part[(size_t)TnFn + i];
    float u = g_part[2 * (size_t)TnFn + i] + g_part[3 * (size_t)TnFn + i];
    float sv = g / (1.f + expf(-g));
    float r = sv * u;
    __nv_bfloat16 hh = __float2bfloat16(r);
    g_Hh[i] = hh;
    g_Hl[i] = __float2bfloat16(r - __bfloat162float(hh));
}

// attention for queries [qbase + blockIdx.x]
__global__ void k_attn(int qbase) {
    int i = qbase + blockIdx.x, hed = blockIdx.y;
    int tid = threadIdx.x;
    __shared__ float q[DHn];
    __shared__ float KV[Tn][DHn + 1];
    __shared__ float p[Tn];
    __shared__ float rmax[4], rsum[4];

    if (tid < DHn) q[tid] = g_Q[(size_t)i * Dn + hed * DHn + tid];
    for (int idx = tid; idx < Tn * DHn; idx += 128) {
        int r = idx >> 6, c = idx & 63;
        KV[r][c] = g_Kc[(size_t)r * Dn + hed * DHn + c];
    }
    __syncthreads();

    float sc;
    if (tid <= i) {
        float s = 0.f;
#pragma unroll
        for (int d = 0; d < DHn; d++) s = fmaf(q[d], KV[tid][d], s);
        sc = s * 0.125f;
    } else sc = -1e9f;

    float m = sc;
#pragma unroll
    for (int o = 16; o > 0; o >>= 1) m = fmaxf(m, __shfl_xor_sync(0xffffffffu, m, o));
    if ((tid & 31) == 0) rmax[tid >> 5] = m;
    __syncthreads();
    m = fmaxf(fmaxf(rmax[0], rmax[1]), fmaxf(rmax[2], rmax[3]));

    float e = expf(sc - m);
    float s = e;
#pragma unroll
    for (int o = 16; o > 0; o >>= 1) s += __shfl_xor_sync(0xffffffffu, s, o);
    if ((tid & 31) == 0) rsum[tid >> 5] = s;
    __syncthreads();
    s = rsum[0] + rsum[1] + rsum[2] + rsum[3];
    p[tid] = e / s;
    __syncthreads();

    for (int idx = tid; idx < Tn * DHn; idx += 128) {
        int r = idx >> 6, c = idx & 63;
        KV[r][c] = g_Vc[(size_t)r * Dn + hed * DHn + c];
    }
    __syncthreads();

    if (tid < DHn) {
        float o = 0.f;
#pragma unroll 8
        for (int j = 0; j < Tn; j++) o = fmaf(p[j], KV[j][tid], o);
        size_t oi = (size_t)i * Dn + hed * DHn + tid;
        __nv_bfloat16 hh = __float2bfloat16(o);
        g_Ah[oi] = hh;
        g_Al[oi] = __float2bfloat16(o - __bfloat162float(hh));
    }
}

// ---- last-layer GEMV path (token 127 only). All device-global pointers are
// resolved IN DEVICE CODE from an integer selector; only harness input
// pointers cross the launch boundary. ----
__global__ void k_gemv(int src, int outoff, const float* __restrict__ W,
                       int K, int N) {
    __shared__ float red[256];
    const __nv_bfloat16 *xh, *xl;
    if (src == 0)      { xh = g_Ah  + (size_t)(Tn - 1) * Dn; xl = g_Al  + (size_t)(Tn - 1) * Dn; }
    else if (src == 1) { xh = g_XNh + (size_t)(Tn - 1) * Dn; xl = g_XNl + (size_t)(Tn - 1) * Dn; }
    else               { xh = g_hrh;                          xl = g_hrl; }
    int nsub = threadIdx.x & 15, ks = threadIdx.x >> 4;
    int n = blockIdx.x * 16 + nsub;
    float s = 0.f;
    for (int k = ks; k < K; k += 16) {
        float x = __bfloat162float(xh[k]) + __bfloat162float(xl[k]);
        s = fmaf(x, W[(size_t)k * N + n], s);
    }
    red[threadIdx.x] = s;
    __syncthreads();
    if (threadIdx.x < 16) {
        float t = 0.f;
#pragma unroll
        for (int j = 0; j < 16; j++) t += red[threadIdx.x + 16 * j];
        g_tmp[outoff + blockIdx.x * 16 + threadIdx.x] = t;
    }
}

// residual add (from g_tmp[0..Dn)) + rmsnorm for token 127. 1 block, 256 thr.
__global__ void k_addnorm_last(const float* __restrict__ w) {
    int d4 = threadIdx.x * 4;
    size_t ro = (size_t)(Tn - 1) * Dn;
    float4 acc = *(const float4*)(g_X + ro + d4);
    float4 pv = *(const float4*)(g_tmp + d4);
    acc.x += pv.x; acc.y += pv.y; acc.z += pv.z; acc.w += pv.w;
    *(float4*)(g_X + ro + d4) = acc;
    float ss = acc.x * acc.x + acc.y * acc.y + acc.z * acc.z + acc.w * acc.w;
    ss = blockReduceSum(ss);
    float inv = rsqrtf(ss / (float)Dn + 1e-5f);
    float4 wv = *(const float4*)(w + d4);
    float xn[4] = { acc.x * inv * wv.x, acc.y * inv * wv.y,
                    acc.z * inv * wv.z, acc.w * inv * wv.w };
#pragma unroll
    for (int i = 0; i < 4; i++) {
        __nv_bfloat16 hh = __float2bfloat16(xn[i]);
        g_XNh[ro + d4 + i] = hh;
        g_XNl[ro + d4 + i] = __float2bfloat16(xn[i] - __bfloat162float(hh));
    }
}

__global__ void k_silu_last() {
    int i = blockIdx.x * blockDim.x + threadIdx.x;
    if (i < Fn) {
        float g = g_tmp[2048 + i], u = g_tmp[5120 + i];
        float sv = g / (1.f + expf(-g));
        float r = sv * u;
        __nv_bfloat16 hh = __float2bfloat16(r);
        g_hrh[i] = hh;
        g_hrl[i] = __float2bfloat16(r - __bfloat162float(hh));
    }
}

// final: x = X[127] + g_tmp[8192..]; rmsnorm(norm_out) -> g_xl. 1 block, 256 thr.
__global__ void k_finalnorm_last(const float* __restrict__ w) {
    int d4 = threadIdx.x * 4;
    size_t ro = (size_t)(Tn - 1) * Dn;
    float4 xv = *(const float4*)(g_X + ro + d4);
    float4 dv = *(const float4*)(g_tmp + 8192 + d4);
    xv.x += dv.x; xv.y += dv.y; xv.z += dv.z; xv.w += dv.w;
    float ss = xv.x * xv.x + xv.y * xv.y + xv.z * xv.z + xv.w * xv.w;
    ss = blockReduceSum(ss);
    float inv = rsqrtf(ss / (float)Dn + 1e-5f);
    float4 wv = *(const float4*)(w + d4);
    *(float4*)(g_xl + d4) = make_float4(xv.x * inv * wv.x, xv.y * inv * wv.y,
                                        xv.z * inv * wv.z, xv.w * inv * wv.w);
}

__global__ void k_logits(const float* __restrict__ emb, float* __restrict__ out) {
    __shared__ float4 xs[Dn / 4];
    for (int i = threadIdx.x; i < Dn / 4; i += blockDim.x)
        xs[i] = ((const float4*)g_xl)[i];
    __syncthreads();
    int warp = threadIdx.x >> 5, lane = threadIdx.x & 31;
    int row = blockIdx.x * 8 + warp;
    if (row < Vn) {
        const float4* e4 = (const float4*)(emb + (size_t)row * Dn);
        float s = 0.f;
#pragma unroll
        for (int k = lane; k < Dn / 4; k += 32) {
            float4 a = e4[k], b = xs[k];
            s += a.x * b.x + a.y * b.y + a.z * b.z + a.w * b.w;
        }
#pragma unroll
        for (int o = 16; o > 0; o >>= 1) s += __shfl_xor_sync(0xffffffffu, s, o);
        if (lane == 0) out[row] = s;
    }
}

// ---- host ----
extern "C" void kernel_launch(void* const* d_in, const int* in_sizes, int n_in,
                              void* d_out, int out_size) {
    const int*   ids       = (const int*)  d_in[0];
    const float* emb       = (const float*)d_in[1];
    const float* Wq        = (const float*)d_in[2];
    const float* Wk        = (const float*)d_in[3];
    const float* Wv        = (const float*)d_in[4];
    const float* Wo        = (const float*)d_in[5];
    const float* Wg        = (const float*)d_in[6];
    const float* Wu        = (const float*)d_in[7];
    const float* Wd        = (const float*)d_in[8];
    const float* attn_norm = (const float*)d_in[9];
    const float* ffn_norm  = (const float*)d_in[10];
    const float* norm_out  = (const float*)d_in[11];
    float* out = (float*)d_out;

    cudaFuncSetAttribute(kg_qkv,  cudaFuncAttributeMaxDynamicSharedMemorySize, SMEM_BYTES);
    cudaFuncSetAttribute(kg_wo,   cudaFuncAttributeMaxDynamicSharedMemorySize, SMEM_BYTES);
    cudaFuncSetAttribute(kg_gu,   cudaFuncAttributeMaxDynamicSharedMemorySize, SMEM_BYTES);
    cudaFuncSetAttribute(kg_down, cudaFuncAttributeMaxDynamicSharedMemorySize, SMEM_BYTES);

    k_embed<<<Tn, 256>>>(ids, emb);

    // layers 0..6: full batched path
    for (int l = 0; l < Ln - 1; l++) {
        const float* wq = Wq + (size_t)l * Dn * Dn;
        const float* wk = Wk + (size_t)l * Dn * Dn;
        const float* wv = Wv + (size_t)l * Dn * Dn;
        const float* wo = Wo + (size_t)l * Dn * Dn;
        const float* wg = Wg + (size_t)l * Dn * Fn;
        const float* wu = Wu + (size_t)l * Dn * Fn;
        const float* wd = Wd + (size_t)l * Fn * Dn;

        k_addnorm<<<Tn, 256>>>(l == 0 ? 0 : 11, attn_norm + (size_t)l * Dn);
        kg_qkv<<<dim3(16, 4, 3), 128, SMEM_BYTES>>>(wq, wk, wv);
        k_qkv_rr<<<Tn, 512>>>();
        k_attn<<<dim3(Tn, Hn), 128>>>(0);
        kg_wo<<<dim3(16, 8), 128, SMEM_BYTES>>>(wo);
        k_addnorm<<<Tn, 256>>>(8, ffn_norm + (size_t)l * Dn);
        kg_gu<<<dim3(44, 2, 2), 128, SMEM_BYTES>>>(wg, wu);
        k_silu<<<TnFn / 256, 256>>>();
        kg_down<<<dim3(16, 11), 128, SMEM_BYTES>>>(wd);
    }

    // layer 7: K/V for all tokens, everything else token 127 only
    {
        const int l = Ln - 1;
        const float* wq = Wq + (size_t)l * Dn * Dn;
        const float* wk = Wk + (size_t)l * Dn * Dn;
        const float* wv = Wv + (size_t)l * Dn * Dn;
        const float* wo = Wo + (size_t)l * Dn * Dn;
        const float* wg = Wg + (size_t)l * Dn * Fn;
        const float* wu = Wu + (size_t)l * Dn * Fn;
        const float* wd = Wd + (size_t)l * Fn * Dn;

        k_addnorm<<<Tn, 256>>>(11, attn_norm + (size_t)l * Dn);
        kg_qkv<<<dim3(16, 4, 3), 128, SMEM_BYTES>>>(wq, wk, wv);
        k_qkv_rr<<<Tn, 512>>>();
        k_attn<<<dim3(1, Hn), 128>>>(Tn - 1);
        k_gemv<<<Dn / 16, 256>>>(0, 0,    wo, Dn, Dn);
        k_addnorm_last<<<1, 256>>>(ffn_norm + (size_t)l * Dn);
        k_gemv<<<Fn / 16, 256>>>(1, 2048, wg, Dn, Fn);
        k_gemv<<<Fn / 16, 256>>>(1, 5120, wu, Dn, Fn);
        k_silu_last<<<(Fn + 255) / 256, 256>>>();
        k_gemv<<<Dn / 16, 256>>>(2, 8192, wd, Fn, Dn);
    }

    k_finalnorm_last<<<1, 256>>>(norm_out);
    k_logits<<<(Vn + 7) / 8, 256>>>(emb, out);
}

// round 14
// speedup vs baseline: 2.0240x; 1.2417x over previous
#include <cuda_runtime.h>
#include <cuda_bf16.h>
#include <math.h>
#include <stdint.h>

#define Tn  128
#define Dn  1024
#define Ln  8
#define Hn  16
#define Fn  2816
#define DHn 64
#define Vn  32000
#define TnDn (Tn*Dn)
#define TnFn (Tn*Fn)

// ---- scratch ----
__device__ float g_X [TnDn];
__device__ float g_Q [TnDn];
__device__ float g_Kc[TnDn];
__device__ float g_Vc[TnDn];
__device__ float g_part[12 * TnDn];
__device__ float g_xl[Dn];
__device__ float g_tmp[12288];                 // last-layer GEMV vectors
__device__ __nv_bfloat16 g_XNh[TnDn], g_XNl[TnDn];
__device__ __nv_bfloat16 g_Ah [TnDn], g_Al [TnDn];
__device__ __nv_bfloat16 g_Hh [TnFn], g_Hl [TnFn];
__device__ __nv_bfloat16 g_hrh[Fn], g_hrl[Fn]; // last-layer silu row

// ---- helpers ----
__device__ __forceinline__ uint32_t smem_u32(const void* p) {
    uint32_t a;
    asm("{ .reg .u64 t; cvta.to.shared.u64 t, %1; cvt.u32.u64 %0, t; }" : "=r"(a) : "l"(p));
    return a;
}
#define LDSM_X4(r0, r1, r2, r3, a) \
    asm volatile("ldmatrix.sync.aligned.m8n8.x4.shared.b16 {%0,%1,%2,%3}, [%4];" \
                 : "=r"(r0), "=r"(r1), "=r"(r2), "=r"(r3) : "r"(a))

__device__ __forceinline__ void mma_bf16(float* d, const uint32_t* a, const uint32_t* b) {
    asm volatile("mma.sync.aligned.m16n8k16.row.col.f32.bf16.bf16.f32 "
                 "{%0,%1,%2,%3}, {%4,%5,%6,%7}, {%8,%9}, {%0,%1,%2,%3};"
                 : "+f"(d[0]), "+f"(d[1]), "+f"(d[2]), "+f"(d[3])
                 : "r"(a[0]), "r"(a[1]), "r"(a[2]), "r"(a[3]), "r"(b[0]), "r"(b[1]));
}
__device__ __forceinline__ void cp16(uint32_t dst, const void* src) {
    asm volatile("cp.async.cg.shared.global [%0], [%1], 16;" :: "r"(dst), "l"(src));
}
#define CP_COMMIT() asm volatile("cp.async.commit_group;")
#define CP_WAIT0()  asm volatile("cp.async.wait_group 0;")

// ---- GEMM core: C[128x64] = Ahl[128,K]*W[K,n0:n0+64). 256 threads (8 warps,
// one 16-row slab per warp), double-buffered smem, identical numerics to r13.
#define PITCHB 144
#define SM_AH(s) ((s) * 18432)
#define SM_AL(s) (36864 + (s) * 18432)
#define SM_BH(s) (73728 + (s) * 9216)
#define SM_BL(s) (92160 + (s) * 9216)
#define SMEM_BYTES 110592

__device__ void gemm_core(const __nv_bfloat16* __restrict__ Ah,
                          const __nv_bfloat16* __restrict__ Al, int lda,
                          const float* __restrict__ B, int ldb,
                          float* __restrict__ Cp, int ldc,
                          int k0, int nkb, int n0)
{
    extern __shared__ unsigned char sm[];
    const uint32_t smb = smem_u32(sm);
    const int tid = threadIdx.x, w = tid >> 5, lane = tid & 31;
    const int gID = lane >> 2, tig = lane & 3;

    float c[8][4] = {};

    const int bkk0 = (tid & 15) << 2;   // B: 4-row k subgroup
    const int bn4  = (tid >> 4) << 2;   // B: 4 consecutive n
    const int a_r = lane & 15, a_h = lane >> 4;
    const int b_nr = ((lane >> 4) << 3) | (lane & 7);
    const int b_kh = (lane >> 3) & 1;

    // prologue: A(0) via cp.async (4 chunks/thread), B(0) into regs
    {
#pragma unroll
        for (int j = 0; j < 4; j++) {
            int idx = tid + j * 256;
            int m = idx >> 3, k8 = (idx & 7) << 3;
            uint32_t off = (uint32_t)m * PITCHB + k8 * 2;
            cp16(smb + SM_AH(0) + off, Ah + (size_t)m * lda + k0 + k8);
            cp16(smb + SM_AL(0) + off, Al + (size_t)m * lda + k0 + k8);
        }
        CP_COMMIT();
    }
    float4 f[4];
#pragma unroll
    for (int j = 0; j < 4; j++)
        f[j] = *(const float4*)(B + (size_t)(k0 + bkk0 + j) * ldb + n0 + bn4);

    for (int it = 0; it < nkb; ++it) {
        const int buf = it & 1;
        const int kc = k0 + it * 64;

        // convert current B regs -> smem(buf), hi/lo
#pragma unroll
        for (int i = 0; i < 4; i++) {
            union { __nv_bfloat16 b[4]; uint2 v; } hb, lb;
#pragma unroll
            for (int j = 0; j < 4; j++) {
                float x = (i == 0) ? f[j].x : (i == 1) ? f[j].y : (i == 2) ? f[j].z : f[j].w;
                __nv_bfloat16 hh = __float2bfloat16(x);
                hb.b[j] = hh;
                lb.b[j] = __float2bfloat16(x - __bfloat162float(hh));
            }
            uint32_t off = (uint32_t)(bn4 + i) * PITCHB + bkk0 * 2;
            *(uint2*)(sm + SM_BH(buf) + off) = hb.v;
            *(uint2*)(sm + SM_BL(buf) + off) = lb.v;
        }
        CP_WAIT0();
        __syncthreads();

        // prefetch next iteration before compute
        if (it + 1 < nkb) {
            const int kn = kc + 64;
#pragma unroll
            for (int j = 0; j < 4; j++) {
                int idx = tid + j * 256;
                int m = idx >> 3, k8 = (idx & 7) << 3;
                uint32_t off = (uint32_t)m * PITCHB + k8 * 2;
                cp16(smb + SM_AH(buf ^ 1) + off, Ah + (size_t)m * lda + kn + k8);
                cp16(smb + SM_AL(buf ^ 1) + off, Al + (size_t)m * lda + kn + k8);
            }
            CP_COMMIT();
#pragma unroll
            for (int j = 0; j < 4; j++)
                f[j] = *(const float4*)(B + (size_t)(kn + bkk0 + j) * ldb + n0 + bn4);
        }

        const uint32_t aH = smb + SM_AH(buf), aL = smb + SM_AL(buf);
        const uint32_t bH = smb + SM_BH(buf), bL = smb + SM_BL(buf);
#pragma unroll
        for (int s = 0; s < 4; s++) {
            uint32_t ah[4], al[4], bh[8][2], bl[8][2];
            uint32_t ao = (uint32_t)(w * 16 + a_r) * PITCHB + (s * 16 + a_h * 8) * 2;
            LDSM_X4(ah[0], ah[1], ah[2], ah[3], aH + ao);
            LDSM_X4(al[0], al[1], al[2], al[3], aL + ao);
#pragma unroll
            for (int np = 0; np < 4; np++) {
                uint32_t bo = (uint32_t)(np * 16 + b_nr) * PITCHB
                            + (s * 16 + b_kh * 8) * 2;
                LDSM_X4(bh[np*2][0], bh[np*2][1], bh[np*2+1][0], bh[np*2+1][1], bH + bo);
                LDSM_X4(bl[np*2][0], bl[np*2][1], bl[np*2+1][0], bl[np*2+1][1], bL + bo);
            }
#pragma unroll
            for (int nt = 0; nt < 8; nt++) {
                mma_bf16(c[nt], ah, bh[nt]);
                mma_bf16(c[nt], ah, bl[nt]);
                mma_bf16(c[nt], al, bh[nt]);
            }
        }
    }

#pragma unroll
    for (int nt = 0; nt < 8; nt++) {
        int row = w * 16 + gID;
        int col = n0 + nt * 8 + tig * 2;
        *(float2*)(Cp + (size_t)row * ldc + col) = make_float2(c[nt][0], c[nt][1]);
        *(float2*)(Cp + (size_t)(row + 8) * ldc + col) = make_float2(c[nt][2], c[nt][3]);
    }
}

// ---- GEMM wrappers ----
__global__ void __launch_bounds__(256)
kg_qkv(const float* __restrict__ Wq, const float* __restrict__ Wk,
       const float* __restrict__ Wv) {
    const float* W = (blockIdx.z == 0) ? Wq : (blockIdx.z == 1) ? Wk : Wv;
    float* Cp = g_part + (size_t)(blockIdx.z * 4 + blockIdx.y) * TnDn;
    gemm_core(g_XNh, g_XNl, Dn, W, Dn, Cp, Dn, blockIdx.y * 256, 4, blockIdx.x * 64);
}
__global__ void __launch_bounds__(256)
kg_wo(const float* __restrict__ Wo) {
    float* Cp = g_part + (size_t)blockIdx.y * TnDn;
    gemm_core(g_Ah, g_Al, Dn, Wo, Dn, Cp, Dn, blockIdx.y * 128, 2, blockIdx.x * 64);
}
__global__ void __launch_bounds__(256)
kg_gu(const float* __restrict__ Wg, const float* __restrict__ Wu) {
    const float* W = (blockIdx.z == 0) ? Wg : Wu;
    float* Cp = g_part + (size_t)(blockIdx.z * 2 + blockIdx.y) * TnFn;
    gemm_core(g_XNh, g_XNl, Dn, W, Fn, Cp, Fn, blockIdx.y * 512, 8, blockIdx.x * 64);
}
__global__ void __launch_bounds__(256)
kg_down(const float* __restrict__ Wd) {
    float* Cp = g_part + (size_t)blockIdx.y * TnDn;
    gemm_core(g_Hh, g_Hl, Fn, Wd, Dn, Cp, Dn, blockIdx.y * 256, 4, blockIdx.x * 64);
}

// ---- elementwise / reductions ----
__device__ __forceinline__ float blockReduceSum(float v) {
    __shared__ float red[32];
    __shared__ float tot;
    int lane = threadIdx.x & 31, warp = threadIdx.x >> 5;
#pragma unroll
    for (int o = 16; o > 0; o >>= 1) v += __shfl_xor_sync(0xffffffffu, v, o);
    if (lane == 0) red[warp] = v;
    __syncthreads();
    int nw = (blockDim.x + 31) >> 5;
    if (warp == 0) {
        float x = (threadIdx.x < nw) ? red[threadIdx.x] : 0.f;
#pragma unroll
        for (int o = 16; o > 0; o >>= 1) x += __shfl_xor_sync(0xffffffffu, x, o);
        if (threadIdx.x == 0) tot = x;
    }
    __syncthreads();
    return tot;
}

__global__ void k_embed(const int* __restrict__ ids, const float* __restrict__ emb) {
    int t = blockIdx.x;
    int row = ids[t];
    const float4* src = (const float4*)(emb + (size_t)row * Dn);
    float4* dst = (float4*)(g_X + (size_t)t * Dn);
    for (int i = threadIdx.x; i < Dn / 4; i += blockDim.x) dst[i] = src[i];
}

__global__ void k_addnorm(int nparts, const float* __restrict__ w) {
    int t = blockIdx.x;
    int d4 = threadIdx.x * 4;
    float4 acc = *(const float4*)(g_X + (size_t)t * Dn + d4);
    for (int p = 0; p < nparts; p++) {
        float4 pv = *(const float4*)(g_part + (size_t)p * TnDn + (size_t)t * Dn + d4);
        acc.x += pv.x; acc.y += pv.y; acc.z += pv.z; acc.w += pv.w;
    }
    *(float4*)(g_X + (size_t)t * Dn + d4) = acc;
    float ss = acc.x * acc.x + acc.y * acc.y + acc.z * acc.z + acc.w * acc.w;
    ss = blockReduceSum(ss);
    float inv = rsqrtf(ss / (float)Dn + 1e-5f);
    float4 wv = *(const float4*)(w + d4);
    float xn[4] = { acc.x * inv * wv.x, acc.y * inv * wv.y,
                    acc.z * inv * wv.z, acc.w * inv * wv.w };
#pragma unroll
    for (int i = 0; i < 4; i++) {
        __nv_bfloat16 hh = __float2bfloat16(xn[i]);
        g_XNh[(size_t)t * Dn + d4 + i] = hh;
        g_XNl[(size_t)t * Dn + d4 + i] = __float2bfloat16(xn[i] - __bfloat162float(hh));
    }
}

// QKV split-K reduce (4 each) + RoPE -> fp32. grid=Tn, block=512.  (r8-identical)
__global__ void k_qkv_rr() {
    int t = blockIdx.x;
    int hh = threadIdx.x >> 5, d = threadIdx.x & 31;
    double invf = pow(10000.0, -(double)d / 32.0);
    double ang = (double)t * invf;
    float c = (float)cos(ang), s = (float)sin(ang);
    int off = t * Dn + hh * DHn + d;
#pragma unroll
    for (int m = 0; m < 3; m++) {
        size_t base = (size_t)(m * 4) * TnDn + off;
        float s0 = 0.f, s1 = 0.f;
#pragma unroll
        for (int p = 0; p < 4; p++) {
            s0 += g_part[base + (size_t)p * TnDn];
            s1 += g_part[base + (size_t)p * TnDn + 32];
        }
        float o0, o1;
        if (m < 2) { o0 = s0 * c - s1 * s; o1 = s1 * c + s0 * s; }
        else       { o0 = s0; o1 = s1; }
        float* dst = (m == 0) ? g_Q : (m == 1) ? g_Kc : g_Vc;
        dst[off] = o0;
        dst[off + 32] = o1;
    }
}

__global__ void k_silu() {
    int i = blockIdx.x * blockDim.x + threadIdx.x;
    float g = g_part[i] + g_part[(size_t)TnFn + i];
    float u = g_part[2 * (size_t)TnFn + i] + g_part[3 * (size_t)TnFn + i];
    float sv = g / (1.f + expf(-g));
    float r = sv * u;
    __nv_bfloat16 hh = __float2bfloat16(r);
    g_Hh[i] = hh;
    g_Hl[i] = __float2bfloat16(r - __bfloat162float(hh));
}

// ---- attention: 16 queries per block. grid (groups, Hn), block 256 (8 warps,
// 2 queries/warp). K/V staged once per 16 queries; exact softmax semantics.
__global__ void __launch_bounds__(256) k_attn(int qg0) {
    int qg = qg0 + blockIdx.x;          // 16-query group index
    int hed = blockIdx.y;
    int tid = threadIdx.x, w = tid >> 5, lane = tid & 31;
    __shared__ float KV[Tn][DHn + 1];
    __shared__ float Qs[16][DHn];
    __shared__ float Ps[16][Tn + 1];

    for (int idx = tid; idx < Tn * DHn; idx += 256) {
        int r = idx >> 6, c = idx & 63;
        KV[r][c] = g_Kc[(size_t)r * Dn + hed * DHn + c];
    }
    for (int idx = tid; idx < 16 * DHn; idx += 256) {
        int r = idx >> 6, c = idx & 63;
        Qs[r][c] = g_Q[(size_t)(qg * 16 + r) * Dn + hed * DHn + c];
    }
    __syncthreads();

#pragma unroll
    for (int sub = 0; sub < 2; sub++) {
        int ql = w * 2 + sub;
        int q = qg * 16 + ql;
        float s[4];
#pragma unroll
        for (int jj = 0; jj < 4; jj++) {
            int j = jj * 32 + lane;
            if (j <= q) {
                float acc = 0.f;
#pragma unroll
                for (int d = 0; d < DHn; d++) acc = fmaf(Qs[ql][d], KV[j][d], acc);
                s[jj] = acc * 0.125f;
            } else s[jj] = -1e9f;
        }
        float m = fmaxf(fmaxf(s[0], s[1]), fmaxf(s[2], s[3]));
#pragma unroll
        for (int o = 16; o > 0; o >>= 1) m = fmaxf(m, __shfl_xor_sync(0xffffffffu, m, o));
        float e[4], sum = 0.f;
#pragma unroll
        for (int jj = 0; jj < 4; jj++) { e[jj] = expf(s[jj] - m); sum += e[jj]; }
#pragma unroll
        for (int o = 16; o > 0; o >>= 1) sum += __shfl_xor_sync(0xffffffffu, sum, o);
#pragma unroll
        for (int jj = 0; jj < 4; jj++) Ps[ql][jj * 32 + lane] = e[jj] / sum;
    }
    __syncthreads();

    // stage V over K
    for (int idx = tid; idx < Tn * DHn; idx += 256) {
        int r = idx >> 6, c = idx & 63;
        KV[r][c] = g_Vc[(size_t)r * Dn + hed * DHn + c];
    }
    __syncthreads();

#pragma unroll
    for (int sub = 0; sub < 2; sub++) {
        int ql = w * 2 + sub;
        int q = qg * 16 + ql;
        float o0 = 0.f, o1 = 0.f;
#pragma unroll 4
        for (int j = 0; j < Tn; j++) {
            float p = Ps[ql][j];
            o0 = fmaf(p, KV[j][lane], o0);
            o1 = fmaf(p, KV[j][lane + 32], o1);
        }
        size_t oi = (size_t)q * Dn + hed * DHn + lane;
        __nv_bfloat16 h0 = __float2bfloat16(o0);
        g_Ah[oi] = h0;
        g_Al[oi] = __float2bfloat16(o0 - __bfloat162float(h0));
        __nv_bfloat16 h1 = __float2bfloat16(o1);
        g_Ah[oi + 32] = h1;
        g_Al[oi + 32] = __float2bfloat16(o1 - __bfloat162float(h1));
    }
}

// ---- last-layer GEMV path (token 127 only; device-resolved globals) ----
__global__ void k_gemv(int src, int outoff, const float* __restrict__ W,
                       int K, int N) {
    __shared__ float red[256];
    const __nv_bfloat16 *xh, *xl;
    if (src == 0)      { xh = g_Ah  + (size_t)(Tn - 1) * Dn; xl = g_Al  + (size_t)(Tn - 1) * Dn; }
    else if (src == 1) { xh = g_XNh + (size_t)(Tn - 1) * Dn; xl = g_XNl + (size_t)(Tn - 1) * Dn; }
    else               { xh = g_hrh;                          xl = g_hrl; }
    int nsub = threadIdx.x & 15, ks = threadIdx.x >> 4;
    int n = blockIdx.x * 16 + nsub;
    float s = 0.f;
    for (int k = ks; k < K; k += 16) {
        float x = __bfloat162float(xh[k]) + __bfloat162float(xl[k]);
        s = fmaf(x, W[(size_t)k * N + n], s);
    }
    red[threadIdx.x] = s;
    __syncthreads();
    if (threadIdx.x < 16) {
        float t = 0.f;
#pragma unroll
        for (int j = 0; j < 16; j++) t += red[threadIdx.x + 16 * j];
        g_tmp[outoff + blockIdx.x * 16 + threadIdx.x] = t;
    }
}

__global__ void k_addnorm_last(const float* __restrict__ w) {
    int d4 = threadIdx.x * 4;
    size_t ro = (size_t)(Tn - 1) * Dn;
    float4 acc = *(const float4*)(g_X + ro + d4);
    float4 pv = *(const float4*)(g_tmp + d4);
    acc.x += pv.x; acc.y += pv.y; acc.z += pv.z; acc.w += pv.w;
    *(float4*)(g_X + ro + d4) = acc;
    float ss = acc.x * acc.x + acc.y * acc.y + acc.z * acc.z + acc.w * acc.w;
    ss = blockReduceSum(ss);
    float inv = rsqrtf(ss / (float)Dn + 1e-5f);
    float4 wv = *(const float4*)(w + d4);
    float xn[4] = { acc.x * inv * wv.x, acc.y * inv * wv.y,
                    acc.z * inv * wv.z, acc.w * inv * wv.w };
#pragma unroll
    for (int i = 0; i < 4; i++) {
        __nv_bfloat16 hh = __float2bfloat16(xn[i]);
        g_XNh[ro + d4 + i] = hh;
        g_XNl[ro + d4 + i] = __float2bfloat16(xn[i] - __bfloat162float(hh));
    }
}

__global__ void k_silu_last() {
    int i = blockIdx.x * blockDim.x + threadIdx.x;
    if (i < Fn) {
        float g = g_tmp[2048 + i], u = g_tmp[5120 + i];
        float sv = g / (1.f + expf(-g));
        float r = sv * u;
        __nv_bfloat16 hh = __float2bfloat16(r);
        g_hrh[i] = hh;
        g_hrl[i] = __float2bfloat16(r - __bfloat162float(hh));
    }
}

__global__ void k_finalnorm_last(const float* __restrict__ w) {
    int d4 = threadIdx.x * 4;
    size_t ro = (size_t)(Tn - 1) * Dn;
    float4 xv = *(const float4*)(g_X + ro + d4);
    float4 dv = *(const float4*)(g_tmp + 8192 + d4);
    xv.x += dv.x; xv.y += dv.y; xv.z += dv.z; xv.w += dv.w;
    float ss = xv.x * xv.x + xv.y * xv.y + xv.z * xv.z + xv.w * xv.w;
    ss = blockReduceSum(ss);
    float inv = rsqrtf(ss / (float)Dn + 1e-5f);
    float4 wv = *(const float4*)(w + d4);
    *(float4*)(g_xl + d4) = make_float4(xv.x * inv * wv.x, xv.y * inv * wv.y,
                                        xv.z * inv * wv.z, xv.w * inv * wv.w);
}

__global__ void k_logits(const float* __restrict__ emb, float* __restrict__ out) {
    __shared__ float4 xs[Dn / 4];
    for (int i = threadIdx.x; i < Dn / 4; i += blockDim.x)
        xs[i] = ((const float4*)g_xl)[i];
    __syncthreads();
    int warp = threadIdx.x >> 5, lane = threadIdx.x & 31;
    int row = blockIdx.x * 8 + warp;
    if (row < Vn) {
        const float4* e4 = (const float4*)(emb + (size_t)row * Dn);
        float s = 0.f;
#pragma unroll
        for (int k = lane; k < Dn / 4; k += 32) {
            float4 a = e4[k], b = xs[k];
            s += a.x * b.x + a.y * b.y + a.z * b.z + a.w * b.w;
        }
#pragma unroll
        for (int o = 16; o > 0; o >>= 1) s += __shfl_xor_sync(0xffffffffu, s, o);
        if (lane == 0) out[row] = s;
    }
}

// ---- host ----
extern "C" void kernel_launch(void* const* d_in, const int* in_sizes, int n_in,
                              void* d_out, int out_size) {
    const int*   ids       = (const int*)  d_in[0];
    const float* emb       = (const float*)d_in[1];
    const float* Wq        = (const float*)d_in[2];
    const float* Wk        = (const float*)d_in[3];
    const float* Wv        = (const float*)d_in[4];
    const float* Wo        = (const float*)d_in[5];
    const float* Wg        = (const float*)d_in[6];
    const float* Wu        = (const float*)d_in[7];
    const float* Wd        = (const float*)d_in[8];
    const float* attn_norm = (const float*)d_in[9];
    const float* ffn_norm  = (const float*)d_in[10];
    const float* norm_out  = (const float*)d_in[11];
    float* out = (float*)d_out;

    cudaFuncSetAttribute(kg_qkv,  cudaFuncAttributeMaxDynamicSharedMemorySize, SMEM_BYTES);
    cudaFuncSetAttribute(kg_wo,   cudaFuncAttributeMaxDynamicSharedMemorySize, SMEM_BYTES);
    cudaFuncSetAttribute(kg_gu,   cudaFuncAttributeMaxDynamicSharedMemorySize, SMEM_BYTES);
    cudaFuncSetAttribute(kg_down, cudaFuncAttributeMaxDynamicSharedMemorySize, SMEM_BYTES);

    k_embed<<<Tn, 256>>>(ids, emb);

    // layers 0..6: full batched path
    for (int l = 0; l < Ln - 1; l++) {
        const float* wq = Wq + (size_t)l * Dn * Dn;
        const float* wk = Wk + (size_t)l * Dn * Dn;
        const float* wv = Wv + (size_t)l * Dn * Dn;
        const float* wo = Wo + (size_t)l * Dn * Dn;
        const float* wg = Wg + (size_t)l * Dn * Fn;
        const float* wu = Wu + (size_t)l * Dn * Fn;
        const float* wd = Wd + (size_t)l * Fn * Dn;

        k_addnorm<<<Tn, 256>>>(l == 0 ? 0 : 11, attn_norm + (size_t)l * Dn);
        kg_qkv<<<dim3(16, 4, 3), 256, SMEM_BYTES>>>(wq, wk, wv);
        k_qkv_rr<<<Tn, 512>>>();
        k_attn<<<dim3(8, Hn), 256>>>(0);
        kg_wo<<<dim3(16, 8), 256, SMEM_BYTES>>>(wo);
        k_addnorm<<<Tn, 256>>>(8, ffn_norm + (size_t)l * Dn);
        kg_gu<<<dim3(44, 2, 2), 256, SMEM_BYTES>>>(wg, wu);
        k_silu<<<TnFn / 256, 256>>>();
        kg_down<<<dim3(16, 11), 256, SMEM_BYTES>>>(wd);
    }

    // layer 7: K/V for all tokens, everything else token 127 only
    {
        const int l = Ln - 1;
        const float* wq = Wq + (size_t)l * Dn * Dn;
        const float* wk = Wk + (size_t)l * Dn * Dn;
        const float* wv = Wv + (size_t)l * Dn * Dn;
        const float* wo = Wo + (size_t)l * Dn * Dn;
        const float* wg = Wg + (size_t)l * Dn * Fn;
        const float* wu = Wu + (size_t)l * Dn * Fn;
        const float* wd = Wd + (size_t)l * Fn * Dn;

        k_addnorm<<<Tn, 256>>>(11, attn_norm + (size_t)l * Dn);
        kg_qkv<<<dim3(16, 4, 3), 256, SMEM_BYTES>>>(wq, wk, wv);
        k_qkv_rr<<<Tn, 512>>>();
        k_attn<<<dim3(1, Hn), 256>>>(7);     // group 7 = queries 112..127
        k_gemv<<<Dn / 16, 256>>>(0, 0,    wo, Dn, Dn);
        k_addnorm_last<<<1, 256>>>(ffn_norm + (size_t)l * Dn);
        k_gemv<<<Fn / 16, 256>>>(1, 2048, wg, Dn, Fn);
        k_gemv<<<Fn / 16, 256>>>(1, 5120, wu, Dn, Fn);
        k_silu_last<<<(Fn + 255) / 256, 256>>>();
        k_gemv<<<Dn / 16, 256>>>(2, 8192, wd, Fn, Dn);
    }

    k_finalnorm_last<<<1, 256>>>(norm_out);
    k_logits<<<(Vn + 7) / 8, 256>>>(emb, out);
}